// round 9
// baseline (speedup 1.0000x reference)
#include <cuda_runtime.h>
#include <cuda_bf16.h>
#include <cstdint>

#define NN   1024
#define C    512
#define EB   16384
#define BATCH 8
#define NLOC 128
#define HM   128
#define NSTEPS 10
#define SB   (BATCH*NLOC*NLOC)   /* 131072 */
#define RNG_N (NN*C)             /* 524288 */

// packed-weight word offsets ([K/2][N] uint32 words); EL1/EL2/ERW contiguous => stacked K=1536
#define WO_EL1 0
#define WO_EL2 131072
#define WO_ERW 262144
#define WO_EFW 393216
#define WO_CL1 655360
#define WO_CL2 786432
#define WO_CRW 917504
#define WO_CFW 1048576
#define WO_MW1 1310720
#define WTOTW  1343488

// ---------------- scratch (no allocation allowed) ----------------
__device__ float g_T[2*NN*C];                 // RelConv fused GEMM out (per side)
__device__ float g_Hs[NN*C], g_Ht[NN*C], g_Rs[NN*C], g_Rt[NN*C];
__device__ float g_Shat[SB], g_S[SB], g_BmT[SB];
__device__ float g_Am[NN*HM], g_Bm[NN*HM];
__device__ float g_M[4*BATCH*NLOC*NLOC];      // dense normalized adjacency [a][b][s][t]
__device__ unsigned g_Wh[WTOTW], g_Wl[WTOTW];
__device__ __nv_bfloat16 g_xh[2*NN*C], g_xl[2*NN*C];
__device__ __nv_bfloat16 g_Yh[4*NN*C], g_Yl[4*NN*C];   // P-applied chunks y1s,y2s,y1t,y2t
__device__ __nv_bfloat16 g_Rsh[NN*C], g_Rsl[NN*C], g_Rth[NN*C], g_Rtl[NN*C];
__device__ __nv_bfloat16 g_Hlnh[2*NN*C], g_Hlnl[2*NN*C];
__device__ __nv_bfloat16 g_Osh[NN*C], g_Osl[NN*C], g_Oth[NN*C], g_Otl[NN*C];

// ---------------- threefry-2x32 (matches JAX) ----------------
__host__ __device__ inline void tf2x32(unsigned k0, unsigned k1,
                                       unsigned x0, unsigned x1,
                                       unsigned &o0, unsigned &o1) {
  unsigned ks2 = k0 ^ k1 ^ 0x1BD11BDAu;
  x0 += k0; x1 += k1;
#define TF_ROT(x,r) (((x)<<(r))|((x)>>(32-(r))))
#define TF_RND(r) { x0 += x1; x1 = TF_ROT(x1,(r)); x1 ^= x0; }
  TF_RND(13) TF_RND(15) TF_RND(26) TF_RND(6)
  x0 += k1;  x1 += ks2 + 1u;
  TF_RND(17) TF_RND(29) TF_RND(16) TF_RND(24)
  x0 += ks2; x1 += k0 + 2u;
  TF_RND(13) TF_RND(15) TF_RND(26) TF_RND(6)
  x0 += k0;  x1 += k1 + 3u;
  TF_RND(17) TF_RND(29) TF_RND(16) TF_RND(24)
  x0 += k1;  x1 += ks2 + 4u;
  TF_RND(13) TF_RND(15) TF_RND(26) TF_RND(6)
  x0 += ks2; x1 += k0 + 5u;
  o0 = x0; o1 = x1;
#undef TF_RND
#undef TF_ROT
}

__device__ __forceinline__ void bfsplit(float v, __nv_bfloat16& h, __nv_bfloat16& l) {
  h = __float2bfloat16(v);
  l = __float2bfloat16(v - __bfloat162float(h));
}

// XLA's Giles erfinv + JAX uniform->normal mapping
__device__ __forceinline__ float bits_to_normal(unsigned bits) {
  float f = __uint_as_float((bits >> 9) | 0x3f800000u) - 1.0f;   // [0,1)
  const float LO = -0.99999994f;
  float u = fmaxf(LO, f * 2.0f + LO);
  float w = -log1pf(-u * u);
  float p;
  if (w < 5.0f) {
    w -= 2.5f;
    p = 2.81022636e-08f;
    p = fmaf(p, w, 3.43273939e-07f);
    p = fmaf(p, w, -3.5233877e-06f);
    p = fmaf(p, w, -4.39150654e-06f);
    p = fmaf(p, w, 0.00021858087f);
    p = fmaf(p, w, -0.00125372503f);
    p = fmaf(p, w, -0.00417768164f);
    p = fmaf(p, w, 0.246640727f);
    p = fmaf(p, w, 1.50140941f);
  } else {
    w = sqrtf(w) - 3.0f;
    p = -0.000200214257f;
    p = fmaf(p, w, 0.000100950558f);
    p = fmaf(p, w, 0.00134934322f);
    p = fmaf(p, w, -0.00367342844f);
    p = fmaf(p, w, 0.00573950773f);
    p = fmaf(p, w, -0.0076224613f);
    p = fmaf(p, w, 0.00943887047f);
    p = fmaf(p, w, 1.00167406f);
    p = fmaf(p, w, 2.83297682f);
  }
  return 1.41421356237309504880f * (p * u);
}

// JAX threefry_partitionable: counter (0, i); bits = out0 ^ out1. raw + bf16 split.
__global__ void rng_kernel(unsigned k0, unsigned k1, float* __restrict__ out,
                           __nv_bfloat16* __restrict__ oh, __nv_bfloat16* __restrict__ ol) {
  unsigned i = blockIdx.x * 256u + threadIdx.x;
  unsigned o0, o1;
  tf2x32(k0, k1, 0u, i, o0, o1);
  float v = bits_to_normal(o0 ^ o1);
  out[i] = v;
  __nv_bfloat16 h, l;
  bfsplit(v, h, l);
  oh[i] = h; ol[i] = l;
}

// fp32 -> bf16 hi/lo splitter
__global__ void split_a(const float* __restrict__ in, __nv_bfloat16* __restrict__ hi,
                        __nv_bfloat16* __restrict__ lo, int n) {
  int i = blockIdx.x * 256 + threadIdx.x;
  if (i >= n) return;
  __nv_bfloat16 h, l;
  bfsplit(in[i], h, l);
  hi[i] = h; lo[i] = l;
}

// weight split+pack: W[K][N] fp32 -> Wh/Wl[K/2][N] bf16x2 words
__global__ void split_pack_w(const float* __restrict__ W, unsigned* __restrict__ Wh,
                             unsigned* __restrict__ Wl, int Khalf, int N) {
  int i = blockIdx.x * 256 + threadIdx.x;
  if (i >= Khalf * N) return;
  int j = i / N, n = i % N;
  float v0 = W[(size_t)(2 * j) * N + n];
  float v1 = W[(size_t)(2 * j + 1) * N + n];
  __nv_bfloat16 h0, l0, h1, l1;
  bfsplit(v0, h0, l0);
  bfsplit(v1, h1, l1);
  __nv_bfloat162 ph = __halves2bfloat162(h0, h1);
  __nv_bfloat162 pl = __halves2bfloat162(l0, l1);
  Wh[i] = *reinterpret_cast<unsigned*>(&ph);
  Wl[i] = *reinterpret_cast<unsigned*>(&pl);
}

// ---------------- dense adjacency build ----------------
// a=0: s-side agg1 (y1[dst] = mean over src): M[src][dst]
// a=1: s-side agg2 (y2[src] = mean over dst): M[dst][src]
// a=2,3: t-side likewise.
__global__ void m_count(const int* __restrict__ eis, const int* __restrict__ eit,
                        float* __restrict__ M) {
  int e = blockIdx.x * 256 + threadIdx.x;
  if (e >= EB) return;
  {
    int src = eis[e], dst = eis[EB + e];
    int b = src >> 7, ls = src & 127, ld = dst & 127;
    atomicAdd(&M[((size_t)0 * BATCH + b) * 16384 + ls * 128 + ld], 1.f);
    atomicAdd(&M[((size_t)1 * BATCH + b) * 16384 + ld * 128 + ls], 1.f);
  }
  {
    int src = eit[e], dst = eit[EB + e];
    int b = src >> 7, ls = src & 127, ld = dst & 127;
    atomicAdd(&M[((size_t)2 * BATCH + b) * 16384 + ls * 128 + ld], 1.f);
    atomicAdd(&M[((size_t)3 * BATCH + b) * 16384 + ld * 128 + ls], 1.f);
  }
}

// column-normalize (output index t is the column): mean = sum/max(cnt,1)
__global__ void m_norm(float* __restrict__ M) {
  int ab = blockIdx.x;                // a*8+b, 32 blocks
  int t = threadIdx.x;                // 128
  float* Mp = M + (size_t)ab * 16384;
  float s = 0.f;
  for (int j = 0; j < 128; j++) s += Mp[j * 128 + t];
  float inv = 1.f / fmaxf(s, 1.f);
  for (int j = 0; j < 128; j++) Mp[j * 128 + t] *= inv;
}

// ---------------- y = P x (batched, fp32, split output) ----------------
__global__ __launch_bounds__(256)
void p_apply(const float* __restrict__ M, const float* __restrict__ xs,
             const float* __restrict__ xt,
             __nv_bfloat16* __restrict__ Yh, __nv_bfloat16* __restrict__ Yl) {
  int a = blockIdx.z, b = blockIdx.y, t0 = blockIdx.x * 16;
  const float* __restrict__ X = (a < 2) ? xs : xt;
  const float* __restrict__ Mp = M + ((size_t)a * BATCH + b) * 16384;
  int tid = threadIdx.x;
  __shared__ float sS[128][16];
#pragma unroll
  for (int l = 0; l < 8; l++) {
    int idx = tid + l * 256;
    int s = idx >> 4, tt = idx & 15;
    sS[s][tt] = Mp[s * 128 + t0 + tt];
  }
  __syncthreads();
  int c = tid;
  float acc0[16] = {}, acc1[16] = {};
  for (int s = 0; s < NLOC; s++) {
    float r0 = X[(size_t)(b * NLOC + s) * C + c];
    float r1 = X[(size_t)(b * NLOC + s) * C + c + 256];
#pragma unroll
    for (int tt = 0; tt < 16; tt++) {
      float sv = sS[s][tt];
      acc0[tt] = fmaf(sv, r0, acc0[tt]);
      acc1[tt] = fmaf(sv, r1, acc1[tt]);
    }
  }
  __nv_bfloat16 h, l;
#pragma unroll
  for (int tt = 0; tt < 16; tt++) {
    size_t i0 = (size_t)a * NN * C + (size_t)(b * NLOC + t0 + tt) * C + c;
    bfsplit(acc0[tt], h, l); Yh[i0] = h;       Yl[i0] = l;
    bfsplit(acc1[tt], h, l); Yh[i0 + 256] = h; Yl[i0 + 256] = l;
  }
}

// ---------------- bf16x3 tensor-core GEMM (3-chunk A, optional transposed raw) ----------------
struct P6 {
  const __nv_bfloat16 *Ah0[2], *Ah1[2], *Ah2[2];   // A chunks: k<512 / 512..1023 / 1024..1535
  const __nv_bfloat16 *Al0[2], *Al1[2], *Al2[2];
  const unsigned *Bh[2], *Bl[2];
  float*          Craw[2];
  __nv_bfloat16  *Chi[2], *Clo[2];
  const float*    bias[2];
  int trT[2];                                      // store Craw transposed [b][h][j]
};

__device__ __forceinline__ void mma16(float* d, const unsigned* a, const unsigned* b) {
  asm volatile(
    "mma.sync.aligned.m16n8k16.row.col.f32.bf16.bf16.f32 "
    "{%0,%1,%2,%3}, {%4,%5,%6,%7}, {%8,%9}, {%0,%1,%2,%3};\n"
    : "+f"(d[0]), "+f"(d[1]), "+f"(d[2]), "+f"(d[3])
    : "r"(a[0]), "r"(a[1]), "r"(a[2]), "r"(a[3]), "r"(b[0]), "r"(b[1]));
}

__device__ __forceinline__ void cpa16(unsigned dst, const void* src) {
  asm volatile("cp.async.cg.shared.global [%0], [%1], 16;" :: "r"(dst), "l"(src));
}
__device__ __forceinline__ void cp_commit() { asm volatile("cp.async.commit_group;"); }

template<int BM, int BN>
constexpr int smem_b() { return (2 * 2 * BM * 12 + 2 * 2 * 8 * (BN + 8)) * 4; }

template<int BM, int BN>
__global__ __launch_bounds__(256) void gemm_bf16(P6 p, int Nn, int K) {
  constexpr int AP = 12, BP = BN + 8;
  constexpr int NAOP = 2 * BM * 2;
  constexpr int NBOP = 2 * 8 * (BN / 4);
  constexpr int WM = BM / 2, WN = BN / 4;
  constexpr int MI = WM / 16, NI = WN / 8;

  const int tid = threadIdx.x;
  const int z = blockIdx.z;
  const __nv_bfloat16* __restrict__ Ah0 = p.Ah0[z];
  const __nv_bfloat16* __restrict__ Ah1p = p.Ah1[z];
  const __nv_bfloat16* __restrict__ Ah2p = p.Ah2[z];
  const __nv_bfloat16* __restrict__ Al0 = p.Al0[z];
  const __nv_bfloat16* __restrict__ Al1p = p.Al1[z];
  const __nv_bfloat16* __restrict__ Al2p = p.Al2[z];
  const unsigned* __restrict__ Bh = p.Bh[z];
  const unsigned* __restrict__ Bl = p.Bl[z];
  float* __restrict__ Craw = p.Craw[z];
  __nv_bfloat16* __restrict__ Chi = p.Chi[z];
  __nv_bfloat16* __restrict__ Clo = p.Clo[z];
  const float* __restrict__ bias = p.bias[z];
  const int trT = p.trT[z];
  const int row0 = blockIdx.y * BM, col0 = blockIdx.x * BN;

  extern __shared__ unsigned smem_u[];
  unsigned* As = smem_u;
  unsigned* Bs = smem_u + 2 * 2 * BM * AP;
  const unsigned as_u = (unsigned)__cvta_generic_to_shared(As);
  const unsigned bs_u = (unsigned)__cvta_generic_to_shared(Bs);

  const int lane = tid & 31;
  const int wid = tid >> 5;
  const int gid = lane >> 2, tg = lane & 3;
  const int wr = wid >> 2, wc = wid & 3;

  float acc[MI][NI][4];
#pragma unroll
  for (int i = 0; i < MI; i++)
#pragma unroll
    for (int j = 0; j < NI; j++)
#pragma unroll
      for (int q = 0; q < 4; q++) acc[i][j][q] = 0.f;

  const int nk = K >> 4;

  auto ldg = [&](int kt, int buf) {
    int chunk = kt >> 9;
    const __nv_bfloat16* Ah = (chunk == 0) ? Ah0 : (chunk == 1) ? Ah1p : Ah2p;
    const __nv_bfloat16* Al = (chunk == 0) ? Al0 : (chunk == 1) ? Al1p : Al2p;
    int ko = kt & 511;
    int ktp = kt >> 1;
#pragma unroll
    for (int i = 0; i < (NAOP + 255) / 256; i++) {
      int idx = tid + i * 256;
      if (NAOP < 256 || NAOP % 256) { if (idx >= NAOP) break; }
      int hl = idx / (BM * 2);
      int rem = idx - hl * (BM * 2);
      int m = rem >> 1, ch = rem & 1;
      const __nv_bfloat16* src = (hl ? Al : Ah) + (size_t)(row0 + m) * 512 + ko + ch * 8;
      unsigned dst = as_u + (unsigned)((((buf * 2 + hl) * BM + m) * AP + ch * 4) * 4);
      cpa16(dst, src);
    }
#pragma unroll
    for (int i = 0; i < (NBOP + 255) / 256; i++) {
      int idx = tid + i * 256;
      if (NBOP < 256 || NBOP % 256) { if (idx >= NBOP) break; }
      int hl = idx / (8 * (BN / 4));
      int rem = idx - hl * (8 * (BN / 4));
      int kp = rem / (BN / 4), n4 = rem % (BN / 4);
      const unsigned* src = (hl ? Bl : Bh) + (size_t)(ktp + kp) * Nn + col0 + n4 * 4;
      unsigned dst = bs_u + (unsigned)((((buf * 2 + hl) * 8 + kp) * BP + n4 * 4) * 4);
      cpa16(dst, src);
    }
  };

  auto compute = [&](int buf) {
    const unsigned* A0 = As + (size_t)((buf * 2 + 0) * BM) * AP;
    const unsigned* A1 = As + (size_t)((buf * 2 + 1) * BM) * AP;
    const unsigned* B0 = Bs + (size_t)((buf * 2 + 0) * 8) * BP;
    const unsigned* B1 = Bs + (size_t)((buf * 2 + 1) * 8) * BP;
    unsigned ah[MI][4], al[MI][4], bh[NI][2], bl[NI][2];
#pragma unroll
    for (int mi = 0; mi < MI; mi++) {
      int m = wr * WM + mi * 16 + gid;
      ah[mi][0] = A0[m * AP + tg];
      ah[mi][1] = A0[(m + 8) * AP + tg];
      ah[mi][2] = A0[m * AP + tg + 4];
      ah[mi][3] = A0[(m + 8) * AP + tg + 4];
      al[mi][0] = A1[m * AP + tg];
      al[mi][1] = A1[(m + 8) * AP + tg];
      al[mi][2] = A1[m * AP + tg + 4];
      al[mi][3] = A1[(m + 8) * AP + tg + 4];
    }
#pragma unroll
    for (int ni = 0; ni < NI; ni++) {
      int n = wc * WN + ni * 8 + gid;
      bh[ni][0] = B0[tg * BP + n];
      bh[ni][1] = B0[(tg + 4) * BP + n];
      bl[ni][0] = B1[tg * BP + n];
      bl[ni][1] = B1[(tg + 4) * BP + n];
    }
#pragma unroll
    for (int mi = 0; mi < MI; mi++)
#pragma unroll
      for (int ni = 0; ni < NI; ni++) {
        mma16(acc[mi][ni], ah[mi], bl[ni]);
        mma16(acc[mi][ni], al[mi], bh[ni]);
        mma16(acc[mi][ni], ah[mi], bh[ni]);
      }
  };

  ldg(0, 0);
  cp_commit();
  for (int t = 0; t < nk; t++) {
    int buf = t & 1;
    if (t + 1 < nk) {
      ldg((t + 1) << 4, buf ^ 1);
      cp_commit();
      asm volatile("cp.async.wait_group 1;");
    } else {
      asm volatile("cp.async.wait_group 0;");
    }
    __syncthreads();
    compute(buf);
    __syncthreads();
  }

#pragma unroll
  for (int mi = 0; mi < MI; mi++) {
#pragma unroll
    for (int ni = 0; ni < NI; ni++) {
      int r = row0 + wr * WM + mi * 16 + gid;
      int c = col0 + wc * WN + ni * 8 + tg * 2;
      float b0 = bias ? bias[c] : 0.f;
      float b1 = bias ? bias[c + 1] : 0.f;
      float v[4] = {acc[mi][ni][0] + b0, acc[mi][ni][1] + b1,
                    acc[mi][ni][2] + b0, acc[mi][ni][3] + b1};
      if (Craw) {
        if (trT) {
          // Craw = BmT[b][h][j]: row r = b*128 + j, col c = h  (Nn==128)
          int b_ = r >> 7, j_ = r & 127;
          int b2_ = (r + 8) >> 7, j2_ = (r + 8) & 127;
          Craw[(size_t)b_ * 16384 + (c) * 128 + j_]       = v[0];
          Craw[(size_t)b_ * 16384 + (c + 1) * 128 + j_]   = v[1];
          Craw[(size_t)b2_ * 16384 + (c) * 128 + j2_]     = v[2];
          Craw[(size_t)b2_ * 16384 + (c + 1) * 128 + j2_] = v[3];
        } else {
          size_t i0 = (size_t)r * Nn + c, i1 = (size_t)(r + 8) * Nn + c;
          Craw[i0] = v[0]; Craw[i0 + 1] = v[1];
          Craw[i1] = v[2]; Craw[i1 + 1] = v[3];
        }
      }
      if (Chi) {
        size_t i0 = (size_t)r * Nn + c, i1 = (size_t)(r + 8) * Nn + c;
        __nv_bfloat16 h, l;
        bfsplit(v[0], h, l); Chi[i0] = h;     Clo[i0] = l;
        bfsplit(v[1], h, l); Chi[i0 + 1] = h; Clo[i0 + 1] = l;
        bfsplit(v[2], h, l); Chi[i1] = h;     Clo[i1] = l;
        bfsplit(v[3], h, l); Chi[i1 + 1] = h; Clo[i1 + 1] = l;
      }
    }
  }
}

// ---------------- relu + LayerNorm (no gather), bf16-split out ----------------
__global__ __launch_bounds__(256)
void ln_split(const float* __restrict__ T,
              const float* __restrict__ gamma, const float* __restrict__ beta,
              __nv_bfloat16* __restrict__ Hhi, __nv_bfloat16* __restrict__ Hlo) {
  int n = blockIdx.x, side = blockIdx.y, t = threadIdx.x;
  const float* Tr = T + (size_t)(side * NN + n) * C;
  int c0 = t, c1 = t + 256;
  float a0 = fmaxf(Tr[c0], 0.f), a1 = fmaxf(Tr[c1], 0.f);
  __shared__ float red[256];
  __shared__ float mu_s, rstd_s;
  red[t] = a0 + a1; __syncthreads();
  for (int o = 128; o > 0; o >>= 1) { if (t < o) red[t] += red[t + o]; __syncthreads(); }
  if (t == 0) mu_s = red[0] * (1.0f / C);
  __syncthreads();
  float mu = mu_s;
  float d0 = a0 - mu, d1 = a1 - mu;
  __syncthreads();
  red[t] = d0 * d0 + d1 * d1; __syncthreads();
  for (int o = 128; o > 0; o >>= 1) { if (t < o) red[t] += red[t + o]; __syncthreads(); }
  if (t == 0) rstd_s = rsqrtf(red[0] * (1.0f / C) + 1e-5f);
  __syncthreads();
  float rstd = rstd_s;
  float v0 = d0 * rstd * gamma[c0] + beta[c0];
  float v1 = d1 * rstd * gamma[c1] + beta[c1];
  size_t base = (size_t)(side * NN + n) * C;
  __nv_bfloat16 h, l;
  bfsplit(v0, h, l); Hhi[base + c0] = h; Hlo[base + c0] = l;
  bfsplit(v1, h, l); Hhi[base + c1] = h; Hlo[base + c1] = l;
}

// ---------------- S_hat = Hs_b @ Ht_b^T ----------------
__global__ __launch_bounds__(256)
void shat_kernel(const float* __restrict__ Hs, const float* __restrict__ Ht,
                 float* __restrict__ Shat) {
  int b = blockIdx.z, s0 = blockIdx.y * 32, t0 = blockIdx.x * 32;
  int tid = threadIdx.x, tx = tid & 15, ty = tid >> 4;
  __shared__ float sA[32][33], sBt[32][33];
  float acc[2][2] = {};
  for (int k0 = 0; k0 < C; k0 += 32) {
#pragma unroll
    for (int l = 0; l < 4; l++) {
      int idx = tid + l * 256;
      int r = idx >> 5, k = idx & 31;
      sA[r][k] = Hs[(b * NLOC + s0 + r) * C + k0 + k];
      sBt[r][k] = Ht[(b * NLOC + t0 + r) * C + k0 + k];
    }
    __syncthreads();
#pragma unroll
    for (int k = 0; k < 32; k++) {
      float a0 = sA[ty * 2][k], a1 = sA[ty * 2 + 1][k];
      float b0 = sBt[tx * 2][k], b1 = sBt[tx * 2 + 1][k];
      acc[0][0] = fmaf(a0, b0, acc[0][0]);
      acc[0][1] = fmaf(a0, b1, acc[0][1]);
      acc[1][0] = fmaf(a1, b0, acc[1][0]);
      acc[1][1] = fmaf(a1, b1, acc[1][1]);
    }
    __syncthreads();
  }
#pragma unroll
  for (int i = 0; i < 2; i++)
#pragma unroll
    for (int j = 0; j < 2; j++)
      Shat[b * (NLOC * NLOC) + (s0 + ty * 2 + i) * NLOC + (t0 + tx * 2 + j)] = acc[i][j];
}

// ---------------- row softmax, dual output ----------------
__global__ void softmax2(const float* __restrict__ in, float* __restrict__ o1,
                         float* __restrict__ o2) {
  int row = blockIdx.x, t = threadIdx.x;
  __shared__ float red[128];
  float v = in[row * 128 + t];
  red[t] = v; __syncthreads();
  for (int o = 64; o > 0; o >>= 1) { if (t < o) red[t] = fmaxf(red[t], red[t + o]); __syncthreads(); }
  float mx = red[0]; __syncthreads();
  float e = expf(v - mx);
  red[t] = e; __syncthreads();
  for (int o = 64; o > 0; o >>= 1) { if (t < o) red[t] += red[t + o]; __syncthreads(); }
  float r = e / red[0];
  o1[row * 128 + t] = r;
  o2[row * 128 + t] = r;
}

// ---------------- R_t = S^T @ R_s, raw + bf16-split ----------------
__global__ __launch_bounds__(256)
void rt_kernel(const float* __restrict__ S, const float* __restrict__ Rs,
               float* __restrict__ Rtraw,
               __nv_bfloat16* __restrict__ Rthi, __nv_bfloat16* __restrict__ Rtlo) {
  int b = blockIdx.y, t0 = blockIdx.x * 16;
  int tid = threadIdx.x;
  __shared__ float sS[128][16];
#pragma unroll
  for (int l = 0; l < 8; l++) {
    int idx = tid + l * 256;
    int s = idx >> 4, tt = idx & 15;
    sS[s][tt] = S[b * (NLOC * NLOC) + s * NLOC + t0 + tt];
  }
  __syncthreads();
  int c = tid;
  float acc0[16] = {}, acc1[16] = {};
  for (int s = 0; s < NLOC; s++) {
    float r0 = Rs[(b * NLOC + s) * C + c];
    float r1 = Rs[(b * NLOC + s) * C + c + 256];
#pragma unroll
    for (int tt = 0; tt < 16; tt++) {
      float sv = sS[s][tt];
      acc0[tt] = fmaf(sv, r0, acc0[tt]);
      acc1[tt] = fmaf(sv, r1, acc1[tt]);
    }
  }
#pragma unroll
  for (int tt = 0; tt < 16; tt++) {
    size_t i0 = (size_t)(b * NLOC + t0 + tt) * C + c;
    Rtraw[i0] = acc0[tt];
    Rtraw[i0 + 256] = acc1[tt];
    __nv_bfloat16 h, l;
    bfsplit(acc0[tt], h, l); Rthi[i0] = h;       Rtlo[i0] = l;
    bfsplit(acc1[tt], h, l); Rthi[i0 + 256] = h; Rtlo[i0 + 256] = l;
  }
}

// ---------------- fused: S_hat += MLP pairwise; S_next = softmax(S_hat row) ----------------
__global__ void pairwise_sm(const float* __restrict__ A, const float* __restrict__ BmT,
                            const float* __restrict__ w2, const float* __restrict__ b2,
                            float* __restrict__ Shat, float* __restrict__ Sout) {
  int bi = blockIdx.x;
  int b = bi >> 7, j = threadIdx.x;
  __shared__ float sA[128], sw[128], red[128];
  sA[j] = A[bi * HM + j];
  sw[j] = w2[j];
  __syncthreads();
  float acc = 0.f;
  const float* Bp = BmT + b * (HM * NLOC) + j;
#pragma unroll 8
  for (int h = 0; h < HM; h++) {
    float d = sA[h] - Bp[h * NLOC];
    acc = fmaf(fmaxf(d, 0.f), sw[h], acc);
  }
  float val = Shat[bi * NLOC + j] + acc + b2[0];
  Shat[bi * NLOC + j] = val;
  // softmax over the row
  red[j] = val; __syncthreads();
  for (int o = 64; o > 0; o >>= 1) { if (j < o) red[j] = fmaxf(red[j], red[j + o]); __syncthreads(); }
  float mx = red[0]; __syncthreads();
  float e = expf(val - mx);
  red[j] = e; __syncthreads();
  for (int o = 64; o > 0; o >>= 1) { if (j < o) red[j] += red[j + o]; __syncthreads(); }
  Sout[bi * NLOC + j] = e / red[0];
}

// ---------------- host side ----------------
struct Ptrs {
  float *T, *Hs, *Ht, *Rs, *Rt, *Shat, *S, *BmT, *Am, *Bm, *M;
  unsigned *Wh, *Wl;
  __nv_bfloat16 *xh, *xl, *Yh, *Yl, *Rsh, *Rsl, *Rth, *Rtl, *Hlnh, *Hlnl, *Osh, *Osl, *Oth, *Otl;
};

// one GNN pair: p_apply done by caller (Yh/Yl filled); here: fused RelConv GEMM (K=1536),
// LN, concat GEMM (K=1024).
static void run_gnn_pair(const __nv_bfloat16* xh_s, const __nv_bfloat16* xl_s,
                         const __nv_bfloat16* xh_t, const __nv_bfloat16* xl_t,
                         size_t oL1, size_t oFW,
                         const float* rb, const float* g, const float* b,
                         const float* Fb,
                         float* rawS, float* rawT,
                         __nv_bfloat16* hiS, __nv_bfloat16* loS,
                         __nv_bfloat16* hiT, __nv_bfloat16* loT,
                         const Ptrs& q) {
  P6 p3 = {};
  for (int z = 0; z < 2; z++) {
    p3.Ah0[z] = q.Yh + (size_t)(z * 2 + 0) * NN * C;
    p3.Al0[z] = q.Yl + (size_t)(z * 2 + 0) * NN * C;
    p3.Ah1[z] = q.Yh + (size_t)(z * 2 + 1) * NN * C;
    p3.Al1[z] = q.Yl + (size_t)(z * 2 + 1) * NN * C;
    p3.Ah2[z] = z ? xh_t : xh_s;
    p3.Al2[z] = z ? xl_t : xl_s;
    p3.Bh[z] = q.Wh + oL1; p3.Bl[z] = q.Wl + oL1;   // stacked [W1;W2;Wr]
    p3.Craw[z] = q.T + (size_t)z * NN * C;
    p3.bias[z] = rb;
  }
  gemm_bf16<64, 128><<<dim3(C / 128, NN / 64, 2), 256, smem_b<64, 128>()>>>(p3, C, 3 * C);

  ln_split<<<dim3(NN, 2), 256>>>(q.T, g, b, q.Hlnh, q.Hlnl);

  P6 pc = {};
  for (int z = 0; z < 2; z++) {
    pc.Ah0[z] = z ? xh_t : xh_s;
    pc.Al0[z] = z ? xl_t : xl_s;
    pc.Ah1[z] = q.Hlnh + (size_t)z * NN * C;
    pc.Al1[z] = q.Hlnl + (size_t)z * NN * C;
    pc.Ah2[z] = pc.Ah1[z]; pc.Al2[z] = pc.Al1[z];
    pc.Bh[z] = q.Wh + oFW; pc.Bl[z] = q.Wl + oFW;
    pc.Craw[z] = z ? rawT : rawS;
    pc.Chi[z] = z ? hiT : hiS;
    pc.Clo[z] = z ? loT : loS;
    pc.bias[z] = Fb;
  }
  gemm_bf16<64, 128><<<dim3(C / 128, NN / 64, 2), 256, smem_b<64, 128>()>>>(pc, C, 2 * C);
}

extern "C" void kernel_launch(void* const* d_in, const int* in_sizes, int n_in,
                              void* d_out, int out_size) {
  const float* x_s  = (const float*)d_in[0];
  const int*   ei_s = (const int*)d_in[1];
  const float* x_t  = (const float*)d_in[4];
  const int*   ei_t = (const int*)d_in[5];
  const float* e_lin1 = (const float*)d_in[8];
  const float* e_lin2 = (const float*)d_in[9];
  const float* e_rw   = (const float*)d_in[10];
  const float* e_rb   = (const float*)d_in[11];
  const float* e_g    = (const float*)d_in[12];
  const float* e_b    = (const float*)d_in[13];
  const float* e_fw   = (const float*)d_in[14];
  const float* e_fb   = (const float*)d_in[15];
  const float* c_lin1 = (const float*)d_in[16];
  const float* c_lin2 = (const float*)d_in[17];
  const float* c_rw   = (const float*)d_in[18];
  const float* c_rb   = (const float*)d_in[19];
  const float* c_g    = (const float*)d_in[20];
  const float* c_b    = (const float*)d_in[21];
  const float* c_fw   = (const float*)d_in[22];
  const float* c_fb   = (const float*)d_in[23];
  const float* m_w1   = (const float*)d_in[24];
  const float* m_b1   = (const float*)d_in[25];
  const float* m_w2   = (const float*)d_in[26];
  const float* m_b2   = (const float*)d_in[27];
  float* out = (float*)d_out;

  Ptrs q;
  cudaGetSymbolAddress((void**)&q.T,    g_T);
  cudaGetSymbolAddress((void**)&q.Hs,   g_Hs);
  cudaGetSymbolAddress((void**)&q.Ht,   g_Ht);
  cudaGetSymbolAddress((void**)&q.Rs,   g_Rs);
  cudaGetSymbolAddress((void**)&q.Rt,   g_Rt);
  cudaGetSymbolAddress((void**)&q.Shat, g_Shat);
  cudaGetSymbolAddress((void**)&q.S,    g_S);
  cudaGetSymbolAddress((void**)&q.BmT,  g_BmT);
  cudaGetSymbolAddress((void**)&q.Am,   g_Am);
  cudaGetSymbolAddress((void**)&q.Bm,   g_Bm);
  cudaGetSymbolAddress((void**)&q.M,    g_M);
  cudaGetSymbolAddress((void**)&q.Wh,   g_Wh);
  cudaGetSymbolAddress((void**)&q.Wl,   g_Wl);
  cudaGetSymbolAddress((void**)&q.xh,   g_xh);
  cudaGetSymbolAddress((void**)&q.xl,   g_xl);
  cudaGetSymbolAddress((void**)&q.Yh,   g_Yh);
  cudaGetSymbolAddress((void**)&q.Yl,   g_Yl);
  cudaGetSymbolAddress((void**)&q.Rsh,  g_Rsh);
  cudaGetSymbolAddress((void**)&q.Rsl,  g_Rsl);
  cudaGetSymbolAddress((void**)&q.Rth,  g_Rth);
  cudaGetSymbolAddress((void**)&q.Rtl,  g_Rtl);
  cudaGetSymbolAddress((void**)&q.Hlnh, g_Hlnh);
  cudaGetSymbolAddress((void**)&q.Hlnl, g_Hlnl);
  cudaGetSymbolAddress((void**)&q.Osh,  g_Osh);
  cudaGetSymbolAddress((void**)&q.Osl,  g_Osl);
  cudaGetSymbolAddress((void**)&q.Oth,  g_Oth);
  cudaGetSymbolAddress((void**)&q.Otl,  g_Otl);

  cudaFuncSetAttribute(gemm_bf16<64, 128>, cudaFuncAttributeMaxDynamicSharedMemorySize, smem_b<64, 128>());
  cudaFuncSetAttribute(gemm_bf16<32, 64>,  cudaFuncAttributeMaxDynamicSharedMemorySize, smem_b<32, 64>());

  // weight split+pack (once per call)
  struct { const float* src; size_t woff; int kh, n; } wj[9] = {
    {e_lin1, WO_EL1, C / 2, C}, {e_lin2, WO_EL2, C / 2, C}, {e_rw, WO_ERW, C / 2, C},
    {e_fw, WO_EFW, C, C},
    {c_lin1, WO_CL1, C / 2, C}, {c_lin2, WO_CL2, C / 2, C}, {c_rw, WO_CRW, C / 2, C},
    {c_fw, WO_CFW, C, C},
    {m_w1, WO_MW1, C / 2, HM},
  };
  for (int i = 0; i < 9; i++) {
    int n = wj[i].kh * wj[i].n;
    split_pack_w<<<(n + 255) / 256, 256>>>(wj[i].src, q.Wh + wj[i].woff,
                                           q.Wl + wj[i].woff, wj[i].kh, wj[i].n);
  }
  split_a<<<NN * C / 256, 256>>>(x_s, q.xh, q.xl, NN * C);
  split_a<<<NN * C / 256, 256>>>(x_t, q.xh + NN * C, q.xl + NN * C, NN * C);

  // dense normalized adjacency
  cudaMemsetAsync(q.M, 0, (size_t)4 * BATCH * NLOC * NLOC * sizeof(float));
  m_count<<<(EB + 255) / 256, 256>>>(ei_s, ei_t, q.M);
  m_norm<<<32, 128>>>(q.M);

  // embedding GNN pair
  p_apply<<<dim3(8, BATCH, 4), 256>>>(q.M, x_s, x_t, q.Yh, q.Yl);
  run_gnn_pair(q.xh, q.xl, q.xh + NN * C, q.xl + NN * C,
               WO_EL1, WO_EFW, e_rb, e_g, e_b, e_fb,
               q.Hs, q.Ht, nullptr, nullptr, nullptr, nullptr, q);

  shat_kernel<<<dim3(4, 4, BATCH), 256>>>(q.Hs, q.Ht, q.Shat);
  softmax2<<<NN, 128>>>(q.Shat, out, q.S);   // S_0 and loop-t0 S

  for (int t = 0; t < NSTEPS; t++) {
    unsigned fk0, fk1;
    tf2x32(0u, 42u, 0u, (unsigned)t, fk0, fk1);
    rng_kernel<<<RNG_N / 256, 256>>>(fk0, fk1, q.Rs, q.Rsh, q.Rsl);
    rt_kernel<<<dim3(8, BATCH), 256>>>(q.S, q.Rs, q.Rt, q.Rth, q.Rtl);
    p_apply<<<dim3(8, BATCH, 4), 256>>>(q.M, q.Rs, q.Rt, q.Yh, q.Yl);
    run_gnn_pair(q.Rsh, q.Rsl, q.Rth, q.Rtl,
                 WO_CL1, WO_CFW, c_rb, c_g, c_b, c_fb,
                 nullptr, nullptr, q.Osh, q.Osl, q.Oth, q.Otl, q);
    // MLP GEMMs: Am = Os@w1 + b1 (raw) ; BmT = (Ot@w1) transposed
    P6 pm = {};
    for (int z = 0; z < 2; z++) {
      pm.Ah0[z] = z ? q.Oth : q.Osh;
      pm.Al0[z] = z ? q.Otl : q.Osl;
      pm.Ah1[z] = pm.Ah0[z]; pm.Al1[z] = pm.Al0[z];
      pm.Ah2[z] = pm.Ah0[z]; pm.Al2[z] = pm.Al0[z];
      pm.Bh[z] = q.Wh + WO_MW1; pm.Bl[z] = q.Wl + WO_MW1;
      pm.Craw[z] = z ? q.BmT : q.Am;
      pm.bias[z] = z ? nullptr : m_b1;
      pm.trT[z] = z;
    }
    gemm_bf16<32, 64><<<dim3(HM / 64, NN / 32, 2), 256, smem_b<32, 64>()>>>(pm, HM, C);
    pairwise_sm<<<NN, 128>>>(q.Am, q.BmT, m_w2, m_b2, q.Shat,
                             (t == NSTEPS - 1) ? (out + SB) : q.S);
  }
}

// round 10
// speedup vs baseline: 1.1463x; 1.1463x over previous
#include <cuda_runtime.h>
#include <cuda_bf16.h>
#include <cstdint>

#define NN   1024
#define C    512
#define EB   16384
#define BATCH 8
#define NLOC 128
#define HM   128
#define NSTEPS 10
#define SB   (BATCH*NLOC*NLOC)   /* 131072 */
#define RNG_N (NN*C)             /* 524288 */

// packed-weight word offsets ([K/2][N] uint32 words)
#define WO_EL1 0
#define WO_EL2 131072
#define WO_ERW 262144
#define WO_EFW 393216
#define WO_CL1 655360
#define WO_CL2 786432
#define WO_CRW 917504
#define WO_CFW 1048576
#define WO_MW1 1310720
#define WTOTW  1343488

// ---------------- scratch (no allocation allowed) ----------------
__device__ float g_T[6*NN*C];
__device__ float g_Hs[NN*C], g_Ht[NN*C], g_Rs[NN*C];
__device__ float g_Shat[SB], g_S[SB], g_BmT[SB];
__device__ float g_Am[NN*HM];
__device__ int g_cnt[4*NN], g_off[4*(NN+1)], g_cur[4*NN], g_lst[4*EB];
// packed split weights (bf16x2 words)
__device__ unsigned g_Wh[WTOTW], g_Wl[WTOTW];
// split activations (bf16 hi/lo, natural [row][512] layout)
__device__ __nv_bfloat16 g_xh[2*NN*C], g_xl[2*NN*C];
__device__ __nv_bfloat16 g_Rsh[NN*C], g_Rsl[NN*C], g_Rth[NN*C], g_Rtl[NN*C];
__device__ __nv_bfloat16 g_Hlnh[2*NN*C], g_Hlnl[2*NN*C];
__device__ __nv_bfloat16 g_Osh[NN*C], g_Osl[NN*C], g_Oth[NN*C], g_Otl[NN*C];

// ---------------- threefry-2x32 (matches JAX) ----------------
__host__ __device__ inline void tf2x32(unsigned k0, unsigned k1,
                                       unsigned x0, unsigned x1,
                                       unsigned &o0, unsigned &o1) {
  unsigned ks2 = k0 ^ k1 ^ 0x1BD11BDAu;
  x0 += k0; x1 += k1;
#define TF_ROT(x,r) (((x)<<(r))|((x)>>(32-(r))))
#define TF_RND(r) { x0 += x1; x1 = TF_ROT(x1,(r)); x1 ^= x0; }
  TF_RND(13) TF_RND(15) TF_RND(26) TF_RND(6)
  x0 += k1;  x1 += ks2 + 1u;
  TF_RND(17) TF_RND(29) TF_RND(16) TF_RND(24)
  x0 += ks2; x1 += k0 + 2u;
  TF_RND(13) TF_RND(15) TF_RND(26) TF_RND(6)
  x0 += k0;  x1 += k1 + 3u;
  TF_RND(17) TF_RND(29) TF_RND(16) TF_RND(24)
  x0 += k1;  x1 += ks2 + 4u;
  TF_RND(13) TF_RND(15) TF_RND(26) TF_RND(6)
  x0 += ks2; x1 += k0 + 5u;
  o0 = x0; o1 = x1;
#undef TF_RND
#undef TF_ROT
}

__device__ __forceinline__ void bfsplit(float v, __nv_bfloat16& h, __nv_bfloat16& l) {
  h = __float2bfloat16(v);
  l = __float2bfloat16(v - __bfloat162float(h));
}

// XLA's Giles erfinv + JAX uniform->normal mapping
__device__ __forceinline__ float bits_to_normal(unsigned bits) {
  float f = __uint_as_float((bits >> 9) | 0x3f800000u) - 1.0f;   // [0,1)
  const float LO = -0.99999994f;
  float u = fmaxf(LO, f * 2.0f + LO);
  float w = -log1pf(-u * u);
  float p;
  if (w < 5.0f) {
    w -= 2.5f;
    p = 2.81022636e-08f;
    p = fmaf(p, w, 3.43273939e-07f);
    p = fmaf(p, w, -3.5233877e-06f);
    p = fmaf(p, w, -4.39150654e-06f);
    p = fmaf(p, w, 0.00021858087f);
    p = fmaf(p, w, -0.00125372503f);
    p = fmaf(p, w, -0.00417768164f);
    p = fmaf(p, w, 0.246640727f);
    p = fmaf(p, w, 1.50140941f);
  } else {
    w = sqrtf(w) - 3.0f;
    p = -0.000200214257f;
    p = fmaf(p, w, 0.000100950558f);
    p = fmaf(p, w, 0.00134934322f);
    p = fmaf(p, w, -0.00367342844f);
    p = fmaf(p, w, 0.00573950773f);
    p = fmaf(p, w, -0.0076224613f);
    p = fmaf(p, w, 0.00943887047f);
    p = fmaf(p, w, 1.00167406f);
    p = fmaf(p, w, 2.83297682f);
  }
  return 1.41421356237309504880f * (p * u);
}

// JAX threefry_partitionable: counter (0, i); bits = out0 ^ out1. raw + bf16 split.
__global__ void rng_kernel(unsigned k0, unsigned k1, float* __restrict__ out,
                           __nv_bfloat16* __restrict__ oh, __nv_bfloat16* __restrict__ ol) {
  unsigned i = blockIdx.x * 256u + threadIdx.x;
  unsigned o0, o1;
  tf2x32(k0, k1, 0u, i, o0, o1);
  float v = bits_to_normal(o0 ^ o1);
  out[i] = v;
  __nv_bfloat16 h, l;
  bfsplit(v, h, l);
  oh[i] = h; ol[i] = l;
}

// fp32 -> bf16 hi/lo splitter (activations)
__global__ void split_a(const float* __restrict__ in, __nv_bfloat16* __restrict__ hi,
                        __nv_bfloat16* __restrict__ lo, int n) {
  int i = blockIdx.x * 256 + threadIdx.x;
  if (i >= n) return;
  __nv_bfloat16 h, l;
  bfsplit(in[i], h, l);
  hi[i] = h; lo[i] = l;
}

// weight split+pack: W[K][N] fp32 -> Wh/Wl[K/2][N] bf16x2 words (k pair in one word)
__global__ void split_pack_w(const float* __restrict__ W, unsigned* __restrict__ Wh,
                             unsigned* __restrict__ Wl, int Khalf, int N) {
  int i = blockIdx.x * 256 + threadIdx.x;
  if (i >= Khalf * N) return;
  int j = i / N, n = i % N;
  float v0 = W[(size_t)(2 * j) * N + n];
  float v1 = W[(size_t)(2 * j + 1) * N + n];
  __nv_bfloat16 h0, l0, h1, l1;
  bfsplit(v0, h0, l0);
  bfsplit(v1, h1, l1);
  __nv_bfloat162 ph = __halves2bfloat162(h0, h1);   // low = k even
  __nv_bfloat162 pl = __halves2bfloat162(l0, l1);
  Wh[i] = *reinterpret_cast<unsigned*>(&ph);
  Wl[i] = *reinterpret_cast<unsigned*>(&pl);
}

// ---------------- CSR build ----------------
__global__ void csr_count(const int* __restrict__ eis, const int* __restrict__ eit,
                          int* __restrict__ cnt) {
  int e = blockIdx.x * 256 + threadIdx.x;
  if (e >= EB) return;
  int ss = eis[e], sd = eis[EB + e];
  atomicAdd(&cnt[0 * NN + sd], 1);
  atomicAdd(&cnt[1 * NN + ss], 1);
  int ts = eit[e], td = eit[EB + e];
  atomicAdd(&cnt[2 * NN + td], 1);
  atomicAdd(&cnt[3 * NN + ts], 1);
}

__global__ void csr_scan(const int* __restrict__ cnt, int* __restrict__ off,
                         int* __restrict__ cur) {
  int a = blockIdx.x, t = threadIdx.x;
  __shared__ int sm[NN];
  int v = cnt[a * NN + t];
  sm[t] = v; __syncthreads();
  for (int o = 1; o < NN; o <<= 1) {
    int u = (t >= o) ? sm[t - o] : 0;
    __syncthreads();
    sm[t] += u;
    __syncthreads();
  }
  int excl = sm[t] - v;
  off[a * (NN + 1) + t] = excl;
  cur[a * NN + t] = excl;
  if (t == NN - 1) off[a * (NN + 1) + NN] = sm[t];
}

__global__ void csr_fill(const int* __restrict__ eis, const int* __restrict__ eit,
                         int* __restrict__ cur, int* __restrict__ lst) {
  int e = blockIdx.x * 256 + threadIdx.x;
  if (e >= EB) return;
  int ss = eis[e], sd = eis[EB + e];
  int p = atomicAdd(&cur[0 * NN + sd], 1); lst[0 * EB + p] = ss;
  p = atomicAdd(&cur[1 * NN + ss], 1);     lst[1 * EB + p] = sd;
  int ts = eit[e], td = eit[EB + e];
  p = atomicAdd(&cur[2 * NN + td], 1);     lst[2 * EB + p] = ts;
  p = atomicAdd(&cur[3 * NN + ts], 1);     lst[3 * EB + p] = td;
}

// ---------------- bf16x3 tensor-core GEMM ----------------
struct P6 {
  const __nv_bfloat16* Ahi[6];   // k<512 half, row stride 512
  const __nv_bfloat16* Alo[6];
  const __nv_bfloat16* Ahi2[6];  // k>=512 (virtual concat)
  const __nv_bfloat16* Alo2[6];
  const unsigned* Bh[6];         // packed [K/2][N] words
  const unsigned* Bl[6];
  float*          Craw[6];       // nullable
  __nv_bfloat16*  Chi[6];        // nullable split epilogue
  __nv_bfloat16*  Clo[6];
  const float*    bias[6];
  int trT[6];                    // store Craw transposed [b][h][j] (Nn must be 128)
};

__device__ __forceinline__ void mma16(float* d, const unsigned* a, const unsigned* b) {
  asm volatile(
    "mma.sync.aligned.m16n8k16.row.col.f32.bf16.bf16.f32 "
    "{%0,%1,%2,%3}, {%4,%5,%6,%7}, {%8,%9}, {%0,%1,%2,%3};\n"
    : "+f"(d[0]), "+f"(d[1]), "+f"(d[2]), "+f"(d[3])
    : "r"(a[0]), "r"(a[1]), "r"(a[2]), "r"(a[3]), "r"(b[0]), "r"(b[1]));
}

__device__ __forceinline__ void cpa16(unsigned dst, const void* src) {
  asm volatile("cp.async.cg.shared.global [%0], [%1], 16;" :: "r"(dst), "l"(src));
}
__device__ __forceinline__ void cp_commit() { asm volatile("cp.async.commit_group;"); }

// smem words: A[2buf][2hl][BM][12] + B[2buf][2hl][8][BN+8]
template<int BM, int BN>
constexpr int smem_b() { return (2 * 2 * BM * 12 + 2 * 2 * 8 * (BN + 8)) * 4; }

// BK=16. A fragments from [m][kpair] rows (pitch 12 words); B from [kpair][n] rows.
template<int BM, int BN>
__global__ __launch_bounds__(256) void gemm_bf16(P6 p, int Nn, int K) {
  constexpr int AP = 12, BP = BN + 8;
  constexpr int NAOP = 2 * BM * 2;          // 16B ops per A tile
  constexpr int NBOP = 2 * 8 * (BN / 4);    // 16B ops per B tile
  constexpr int WM = BM / 2, WN = BN / 4;
  constexpr int MI = WM / 16, NI = WN / 8;

  const int tid = threadIdx.x;
  const int z = blockIdx.z;
  const __nv_bfloat16* __restrict__ Ahi = p.Ahi[z];
  const __nv_bfloat16* __restrict__ Alo = p.Alo[z];
  const __nv_bfloat16* __restrict__ Ahi2 = p.Ahi2[z];
  const __nv_bfloat16* __restrict__ Alo2 = p.Alo2[z];
  const unsigned* __restrict__ Bh = p.Bh[z];
  const unsigned* __restrict__ Bl = p.Bl[z];
  float* __restrict__ Craw = p.Craw[z];
  __nv_bfloat16* __restrict__ Chi = p.Chi[z];
  __nv_bfloat16* __restrict__ Clo = p.Clo[z];
  const float* __restrict__ bias = p.bias[z];
  const int trT = p.trT[z];
  const int row0 = blockIdx.y * BM, col0 = blockIdx.x * BN;

  extern __shared__ unsigned smem_u[];
  unsigned* As = smem_u;
  unsigned* Bs = smem_u + 2 * 2 * BM * AP;
  const unsigned as_u = (unsigned)__cvta_generic_to_shared(As);
  const unsigned bs_u = (unsigned)__cvta_generic_to_shared(Bs);

  const int lane = tid & 31;
  const int wid = tid >> 5;
  const int gid = lane >> 2, tg = lane & 3;
  const int wr = wid >> 2, wc = wid & 3;   // 2 x 4 warps

  float acc[MI][NI][4];
#pragma unroll
  for (int i = 0; i < MI; i++)
#pragma unroll
    for (int j = 0; j < NI; j++)
#pragma unroll
      for (int q = 0; q < 4; q++) acc[i][j][q] = 0.f;

  const int nk = K >> 4;

  auto ldg = [&](int kt, int buf) {
    const __nv_bfloat16* Ah = (kt >= 512) ? Ahi2 : Ahi;
    const __nv_bfloat16* Al = (kt >= 512) ? Alo2 : Alo;
    int ko = kt & 511;
    int ktp = kt >> 1;
#pragma unroll
    for (int i = 0; i < (NAOP + 255) / 256; i++) {
      int idx = tid + i * 256;
      if (NAOP < 256 || NAOP % 256) { if (idx >= NAOP) break; }
      int hl = idx / (BM * 2);
      int rem = idx - hl * (BM * 2);
      int m = rem >> 1, ch = rem & 1;
      const __nv_bfloat16* src = (hl ? Al : Ah) + (size_t)(row0 + m) * 512 + ko + ch * 8;
      unsigned dst = as_u + (unsigned)((((buf * 2 + hl) * BM + m) * AP + ch * 4) * 4);
      cpa16(dst, src);
    }
#pragma unroll
    for (int i = 0; i < (NBOP + 255) / 256; i++) {
      int idx = tid + i * 256;
      if (NBOP < 256 || NBOP % 256) { if (idx >= NBOP) break; }
      int hl = idx / (8 * (BN / 4));
      int rem = idx - hl * (8 * (BN / 4));
      int kp = rem / (BN / 4), n4 = rem % (BN / 4);
      const unsigned* src = (hl ? Bl : Bh) + (size_t)(ktp + kp) * Nn + col0 + n4 * 4;
      unsigned dst = bs_u + (unsigned)((((buf * 2 + hl) * 8 + kp) * BP + n4 * 4) * 4);
      cpa16(dst, src);
    }
  };

  auto compute = [&](int buf) {
    const unsigned* A0 = As + (size_t)((buf * 2 + 0) * BM) * AP;
    const unsigned* A1 = As + (size_t)((buf * 2 + 1) * BM) * AP;
    const unsigned* B0 = Bs + (size_t)((buf * 2 + 0) * 8) * BP;
    const unsigned* B1 = Bs + (size_t)((buf * 2 + 1) * 8) * BP;
    unsigned ah[MI][4], al[MI][4], bh[NI][2], bl[NI][2];
#pragma unroll
    for (int mi = 0; mi < MI; mi++) {
      int m = wr * WM + mi * 16 + gid;
      ah[mi][0] = A0[m * AP + tg];
      ah[mi][1] = A0[(m + 8) * AP + tg];
      ah[mi][2] = A0[m * AP + tg + 4];
      ah[mi][3] = A0[(m + 8) * AP + tg + 4];
      al[mi][0] = A1[m * AP + tg];
      al[mi][1] = A1[(m + 8) * AP + tg];
      al[mi][2] = A1[m * AP + tg + 4];
      al[mi][3] = A1[(m + 8) * AP + tg + 4];
    }
#pragma unroll
    for (int ni = 0; ni < NI; ni++) {
      int n = wc * WN + ni * 8 + gid;
      bh[ni][0] = B0[tg * BP + n];
      bh[ni][1] = B0[(tg + 4) * BP + n];
      bl[ni][0] = B1[tg * BP + n];
      bl[ni][1] = B1[(tg + 4) * BP + n];
    }
#pragma unroll
    for (int mi = 0; mi < MI; mi++)
#pragma unroll
      for (int ni = 0; ni < NI; ni++) {
        mma16(acc[mi][ni], ah[mi], bl[ni]);
        mma16(acc[mi][ni], al[mi], bh[ni]);
        mma16(acc[mi][ni], ah[mi], bh[ni]);
      }
  };

  ldg(0, 0);
  cp_commit();
  for (int t = 0; t < nk; t++) {
    int buf = t & 1;
    if (t + 1 < nk) {
      ldg((t + 1) << 4, buf ^ 1);
      cp_commit();
      asm volatile("cp.async.wait_group 1;");
    } else {
      asm volatile("cp.async.wait_group 0;");
    }
    __syncthreads();
    compute(buf);
    __syncthreads();
  }

#pragma unroll
  for (int mi = 0; mi < MI; mi++) {
#pragma unroll
    for (int ni = 0; ni < NI; ni++) {
      int r = row0 + wr * WM + mi * 16 + gid;
      int c = col0 + wc * WN + ni * 8 + tg * 2;
      float b0 = bias ? bias[c] : 0.f;
      float b1 = bias ? bias[c + 1] : 0.f;
      float v[4] = {acc[mi][ni][0] + b0, acc[mi][ni][1] + b1,
                    acc[mi][ni][2] + b0, acc[mi][ni][3] + b1};
      if (Craw) {
        if (trT) {
          int b_ = r >> 7, j_ = r & 127;
          int b2_ = (r + 8) >> 7, j2_ = (r + 8) & 127;
          Craw[(size_t)b_ * 16384 + (c) * 128 + j_]       = v[0];
          Craw[(size_t)b_ * 16384 + (c + 1) * 128 + j_]   = v[1];
          Craw[(size_t)b2_ * 16384 + (c) * 128 + j2_]     = v[2];
          Craw[(size_t)b2_ * 16384 + (c + 1) * 128 + j2_] = v[3];
        } else {
          size_t i0 = (size_t)r * Nn + c, i1 = (size_t)(r + 8) * Nn + c;
          Craw[i0] = v[0]; Craw[i0 + 1] = v[1];
          Craw[i1] = v[2]; Craw[i1 + 1] = v[3];
        }
      }
      if (Chi) {
        size_t i0 = (size_t)r * Nn + c, i1 = (size_t)(r + 8) * Nn + c;
        __nv_bfloat16 h, l;
        bfsplit(v[0], h, l); Chi[i0] = h;     Clo[i0] = l;
        bfsplit(v[1], h, l); Chi[i0 + 1] = h; Clo[i0 + 1] = l;
        bfsplit(v[2], h, l); Chi[i1] = h;     Clo[i1] = l;
        bfsplit(v[3], h, l); Chi[i1 + 1] = h; Clo[i1 + 1] = l;
      }
    }
  }
}

// ---------------- fused edge-mean + ReLU + LayerNorm (both sides), bf16-split out ----------------
__global__ __launch_bounds__(256)
void agg_ln(const float* __restrict__ T, const int* __restrict__ off,
            const int* __restrict__ lst,
            const float* __restrict__ gamma, const float* __restrict__ beta,
            __nv_bfloat16* __restrict__ Hhi, __nv_bfloat16* __restrict__ Hlo) {
  int n = blockIdx.x, side = blockIdx.y, t = threadIdx.x;
  const float* T1 = T + (size_t)(side * 3 + 0) * NN * C;
  const float* T2 = T + (size_t)(side * 3 + 1) * NN * C;
  const float* TR = T + (size_t)(side * 3 + 2) * NN * C;
  const int* inoff = off + (side * 2 + 0) * (NN + 1);
  const int* outoff = off + (side * 2 + 1) * (NN + 1);
  const int* inlst = lst + (size_t)(side * 2 + 0) * EB;
  const int* outlst = lst + (size_t)(side * 2 + 1) * EB;
  int c0 = t, c1 = t + 256;
  float a0 = TR[n * C + c0], a1 = TR[n * C + c1];
  {
    int s = inoff[n], e = inoff[n + 1];
    float s0 = 0.f, s1 = 0.f;
    for (int j = s; j < e; j++) {
      int m = inlst[j];
      s0 += T1[m * C + c0];
      s1 += T1[m * C + c1];
    }
    float inv = 1.0f / (float)max(e - s, 1);
    a0 += s0 * inv; a1 += s1 * inv;
  }
  {
    int s = outoff[n], e = outoff[n + 1];
    float s0 = 0.f, s1 = 0.f;
    for (int j = s; j < e; j++) {
      int m = outlst[j];
      s0 += T2[m * C + c0];
      s1 += T2[m * C + c1];
    }
    float inv = 1.0f / (float)max(e - s, 1);
    a0 += s0 * inv; a1 += s1 * inv;
  }
  a0 = fmaxf(a0, 0.f); a1 = fmaxf(a1, 0.f);
  __shared__ float red[256];
  __shared__ float mu_s, rstd_s;
  red[t] = a0 + a1; __syncthreads();
  for (int o = 128; o > 0; o >>= 1) { if (t < o) red[t] += red[t + o]; __syncthreads(); }
  if (t == 0) mu_s = red[0] * (1.0f / C);
  __syncthreads();
  float mu = mu_s;
  float d0 = a0 - mu, d1 = a1 - mu;
  __syncthreads();
  red[t] = d0 * d0 + d1 * d1; __syncthreads();
  for (int o = 128; o > 0; o >>= 1) { if (t < o) red[t] += red[t + o]; __syncthreads(); }
  if (t == 0) rstd_s = rsqrtf(red[0] * (1.0f / C) + 1e-5f);
  __syncthreads();
  float rstd = rstd_s;
  float v0 = d0 * rstd * gamma[c0] + beta[c0];
  float v1 = d1 * rstd * gamma[c1] + beta[c1];
  size_t base = (size_t)(side * NN + n) * C;
  __nv_bfloat16 h, l;
  bfsplit(v0, h, l); Hhi[base + c0] = h; Hlo[base + c0] = l;
  bfsplit(v1, h, l); Hhi[base + c1] = h; Hlo[base + c1] = l;
}

// ---------------- S_hat = Hs_b @ Ht_b^T ----------------
__global__ __launch_bounds__(256)
void shat_kernel(const float* __restrict__ Hs, const float* __restrict__ Ht,
                 float* __restrict__ Shat) {
  int b = blockIdx.z, s0 = blockIdx.y * 32, t0 = blockIdx.x * 32;
  int tid = threadIdx.x, tx = tid & 15, ty = tid >> 4;
  __shared__ float sA[32][33], sBt[32][33];
  float acc[2][2] = {};
  for (int k0 = 0; k0 < C; k0 += 32) {
#pragma unroll
    for (int l = 0; l < 4; l++) {
      int idx = tid + l * 256;
      int r = idx >> 5, k = idx & 31;
      sA[r][k] = Hs[(b * NLOC + s0 + r) * C + k0 + k];
      sBt[r][k] = Ht[(b * NLOC + t0 + r) * C + k0 + k];
    }
    __syncthreads();
#pragma unroll
    for (int k = 0; k < 32; k++) {
      float a0 = sA[ty * 2][k], a1 = sA[ty * 2 + 1][k];
      float b0 = sBt[tx * 2][k], b1 = sBt[tx * 2 + 1][k];
      acc[0][0] = fmaf(a0, b0, acc[0][0]);
      acc[0][1] = fmaf(a0, b1, acc[0][1]);
      acc[1][0] = fmaf(a1, b0, acc[1][0]);
      acc[1][1] = fmaf(a1, b1, acc[1][1]);
    }
    __syncthreads();
  }
#pragma unroll
  for (int i = 0; i < 2; i++)
#pragma unroll
    for (int j = 0; j < 2; j++)
      Shat[b * (NLOC * NLOC) + (s0 + ty * 2 + i) * NLOC + (t0 + tx * 2 + j)] = acc[i][j];
}

// ---------------- row softmax, dual output ----------------
__global__ void softmax2(const float* __restrict__ in, float* __restrict__ o1,
                         float* __restrict__ o2) {
  int row = blockIdx.x, t = threadIdx.x;
  __shared__ float red[128];
  float v = in[row * 128 + t];
  red[t] = v; __syncthreads();
  for (int o = 64; o > 0; o >>= 1) { if (t < o) red[t] = fmaxf(red[t], red[t + o]); __syncthreads(); }
  float mx = red[0]; __syncthreads();
  float e = expf(v - mx);
  red[t] = e; __syncthreads();
  for (int o = 64; o > 0; o >>= 1) { if (t < o) red[t] += red[t + o]; __syncthreads(); }
  float r = e / red[0];
  o1[row * 128 + t] = r;
  o2[row * 128 + t] = r;
}

// ---------------- R_t = S^T @ R_s, bf16-split output ----------------
__global__ __launch_bounds__(256)
void rt_kernel(const float* __restrict__ S, const float* __restrict__ Rs,
               __nv_bfloat16* __restrict__ Rthi, __nv_bfloat16* __restrict__ Rtlo) {
  int b = blockIdx.y, t0 = blockIdx.x * 16;
  int tid = threadIdx.x;
  __shared__ float sS[128][16];
#pragma unroll
  for (int l = 0; l < 8; l++) {
    int idx = tid + l * 256;
    int s = idx >> 4, tt = idx & 15;
    sS[s][tt] = S[b * (NLOC * NLOC) + s * NLOC + t0 + tt];
  }
  __syncthreads();
  int c = tid;
  float acc0[16] = {}, acc1[16] = {};
  for (int s = 0; s < NLOC; s++) {
    float r0 = Rs[(b * NLOC + s) * C + c];
    float r1 = Rs[(b * NLOC + s) * C + c + 256];
#pragma unroll
    for (int tt = 0; tt < 16; tt++) {
      float sv = sS[s][tt];
      acc0[tt] = fmaf(sv, r0, acc0[tt]);
      acc1[tt] = fmaf(sv, r1, acc1[tt]);
    }
  }
#pragma unroll
  for (int tt = 0; tt < 16; tt++) {
    size_t i0 = (size_t)(b * NLOC + t0 + tt) * C + c;
    __nv_bfloat16 h, l;
    bfsplit(acc0[tt], h, l); Rthi[i0] = h;       Rtlo[i0] = l;
    bfsplit(acc1[tt], h, l); Rthi[i0 + 256] = h; Rtlo[i0 + 256] = l;
  }
}

// ---------------- fused: S_hat += MLP pairwise; S_next = softmax(row) ----------------
__global__ void pairwise_sm(const float* __restrict__ A, const float* __restrict__ BmT,
                            const float* __restrict__ w2, const float* __restrict__ b2,
                            float* __restrict__ Shat, float* __restrict__ Sout) {
  int bi = blockIdx.x;
  int b = bi >> 7, j = threadIdx.x;
  __shared__ float sA[128], sw[128], red[128];
  sA[j] = A[bi * HM + j];
  sw[j] = w2[j];
  __syncthreads();
  float acc = 0.f;
  const float* Bp = BmT + b * (HM * NLOC) + j;
#pragma unroll 8
  for (int h = 0; h < HM; h++) {
    float d = sA[h] - Bp[h * NLOC];
    acc = fmaf(fmaxf(d, 0.f), sw[h], acc);
  }
  float val = Shat[bi * NLOC + j] + acc + b2[0];
  Shat[bi * NLOC + j] = val;
  red[j] = val; __syncthreads();
  for (int o = 64; o > 0; o >>= 1) { if (j < o) red[j] = fmaxf(red[j], red[j + o]); __syncthreads(); }
  float mx = red[0]; __syncthreads();
  float e = expf(val - mx);
  red[j] = e; __syncthreads();
  for (int o = 64; o > 0; o >>= 1) { if (j < o) red[j] += red[j + o]; __syncthreads(); }
  Sout[bi * NLOC + j] = e / red[0];
}

// ---------------- host side ----------------
struct Ptrs {
  float *T, *Hs, *Ht, *Rs, *Shat, *S, *BmT, *Am;
  unsigned *Wh, *Wl;
  __nv_bfloat16 *xh, *xl, *Rsh, *Rsl, *Rth, *Rtl, *Hlnh, *Hlnl, *Osh, *Osl, *Oth, *Otl;
  int *cnt, *off, *cur, *lst;
};

static void run_gnn_pair(const __nv_bfloat16* ah_s, const __nv_bfloat16* al_s,
                         const __nv_bfloat16* ah_t, const __nv_bfloat16* al_t,
                         size_t oL1, size_t oL2, size_t oRW, size_t oFW,
                         const float* rb, const float* g, const float* b,
                         const float* Fb,
                         float* rawS, float* rawT,
                         __nv_bfloat16* hiS, __nv_bfloat16* loS,
                         __nv_bfloat16* hiT, __nv_bfloat16* loT,
                         const Ptrs& q) {
  P6 p3 = {};
  for (int z = 0; z < 6; z++) {
    int side = z / 3, w = z % 3;
    p3.Ahi[z] = side ? ah_t : ah_s;
    p3.Alo[z] = side ? al_t : al_s;
    p3.Ahi2[z] = p3.Ahi[z]; p3.Alo2[z] = p3.Alo[z];
    size_t wo = (w == 0) ? oL1 : (w == 1) ? oL2 : oRW;
    p3.Bh[z] = q.Wh + wo; p3.Bl[z] = q.Wl + wo;
    p3.Craw[z] = q.T + (size_t)z * NN * C;
    p3.bias[z] = (w == 2) ? rb : nullptr;
  }
  gemm_bf16<128, 128><<<dim3(C / 128, NN / 128, 6), 256, smem_b<128, 128>()>>>(p3, C, C);

  agg_ln<<<dim3(NN, 2), 256>>>(q.T, q.off, q.lst, g, b, q.Hlnh, q.Hlnl);

  // virtual-concat GEMM: [x|H] @ Fw (K=1024)
  P6 pc = {};
  for (int z = 0; z < 2; z++) {
    pc.Ahi[z] = z ? ah_t : ah_s;
    pc.Alo[z] = z ? al_t : al_s;
    pc.Ahi2[z] = q.Hlnh + (size_t)z * NN * C;
    pc.Alo2[z] = q.Hlnl + (size_t)z * NN * C;
    pc.Bh[z] = q.Wh + oFW; pc.Bl[z] = q.Wl + oFW;
    pc.Craw[z] = z ? rawT : rawS;
    pc.Chi[z] = z ? hiT : hiS;
    pc.Clo[z] = z ? loT : loS;
    pc.bias[z] = Fb;
  }
  gemm_bf16<64, 128><<<dim3(C / 128, NN / 64, 2), 256, smem_b<64, 128>()>>>(pc, C, 2 * C);
}

extern "C" void kernel_launch(void* const* d_in, const int* in_sizes, int n_in,
                              void* d_out, int out_size) {
  const float* x_s  = (const float*)d_in[0];
  const int*   ei_s = (const int*)d_in[1];
  const float* x_t  = (const float*)d_in[4];
  const int*   ei_t = (const int*)d_in[5];
  const float* e_lin1 = (const float*)d_in[8];
  const float* e_lin2 = (const float*)d_in[9];
  const float* e_rw   = (const float*)d_in[10];
  const float* e_rb   = (const float*)d_in[11];
  const float* e_g    = (const float*)d_in[12];
  const float* e_b    = (const float*)d_in[13];
  const float* e_fw   = (const float*)d_in[14];
  const float* e_fb   = (const float*)d_in[15];
  const float* c_lin1 = (const float*)d_in[16];
  const float* c_lin2 = (const float*)d_in[17];
  const float* c_rw   = (const float*)d_in[18];
  const float* c_rb   = (const float*)d_in[19];
  const float* c_g    = (const float*)d_in[20];
  const float* c_b    = (const float*)d_in[21];
  const float* c_fw   = (const float*)d_in[22];
  const float* c_fb   = (const float*)d_in[23];
  const float* m_w1   = (const float*)d_in[24];
  const float* m_b1   = (const float*)d_in[25];
  const float* m_w2   = (const float*)d_in[26];
  const float* m_b2   = (const float*)d_in[27];
  float* out = (float*)d_out;

  Ptrs q;
  cudaGetSymbolAddress((void**)&q.T,    g_T);
  cudaGetSymbolAddress((void**)&q.Hs,   g_Hs);
  cudaGetSymbolAddress((void**)&q.Ht,   g_Ht);
  cudaGetSymbolAddress((void**)&q.Rs,   g_Rs);
  cudaGetSymbolAddress((void**)&q.Shat, g_Shat);
  cudaGetSymbolAddress((void**)&q.S,    g_S);
  cudaGetSymbolAddress((void**)&q.BmT,  g_BmT);
  cudaGetSymbolAddress((void**)&q.Am,   g_Am);
  cudaGetSymbolAddress((void**)&q.Wh,   g_Wh);
  cudaGetSymbolAddress((void**)&q.Wl,   g_Wl);
  cudaGetSymbolAddress((void**)&q.xh,   g_xh);
  cudaGetSymbolAddress((void**)&q.xl,   g_xl);
  cudaGetSymbolAddress((void**)&q.Rsh,  g_Rsh);
  cudaGetSymbolAddress((void**)&q.Rsl,  g_Rsl);
  cudaGetSymbolAddress((void**)&q.Rth,  g_Rth);
  cudaGetSymbolAddress((void**)&q.Rtl,  g_Rtl);
  cudaGetSymbolAddress((void**)&q.Hlnh, g_Hlnh);
  cudaGetSymbolAddress((void**)&q.Hlnl, g_Hlnl);
  cudaGetSymbolAddress((void**)&q.Osh,  g_Osh);
  cudaGetSymbolAddress((void**)&q.Osl,  g_Osl);
  cudaGetSymbolAddress((void**)&q.Oth,  g_Oth);
  cudaGetSymbolAddress((void**)&q.Otl,  g_Otl);
  cudaGetSymbolAddress((void**)&q.cnt,  g_cnt);
  cudaGetSymbolAddress((void**)&q.off,  g_off);
  cudaGetSymbolAddress((void**)&q.cur,  g_cur);
  cudaGetSymbolAddress((void**)&q.lst,  g_lst);

  cudaFuncSetAttribute(gemm_bf16<128, 128>, cudaFuncAttributeMaxDynamicSharedMemorySize, smem_b<128, 128>());
  cudaFuncSetAttribute(gemm_bf16<64, 128>,  cudaFuncAttributeMaxDynamicSharedMemorySize, smem_b<64, 128>());
  cudaFuncSetAttribute(gemm_bf16<32, 64>,   cudaFuncAttributeMaxDynamicSharedMemorySize, smem_b<32, 64>());

  // weight split+pack (once per call)
  struct { const float* src; size_t woff; int kh, n; } wj[9] = {
    {e_lin1, WO_EL1, C / 2, C}, {e_lin2, WO_EL2, C / 2, C}, {e_rw, WO_ERW, C / 2, C},
    {e_fw, WO_EFW, C, C},
    {c_lin1, WO_CL1, C / 2, C}, {c_lin2, WO_CL2, C / 2, C}, {c_rw, WO_CRW, C / 2, C},
    {c_fw, WO_CFW, C, C},
    {m_w1, WO_MW1, C / 2, HM},
  };
  for (int i = 0; i < 9; i++) {
    int n = wj[i].kh * wj[i].n;
    split_pack_w<<<(n + 255) / 256, 256>>>(wj[i].src, q.Wh + wj[i].woff,
                                           q.Wl + wj[i].woff, wj[i].kh, wj[i].n);
  }
  split_a<<<NN * C / 256, 256>>>(x_s, q.xh, q.xl, NN * C);
  split_a<<<NN * C / 256, 256>>>(x_t, q.xh + NN * C, q.xl + NN * C, NN * C);

  // CSR build
  cudaMemsetAsync(q.cnt, 0, 4 * NN * sizeof(int));
  csr_count<<<(EB + 255) / 256, 256>>>(ei_s, ei_t, q.cnt);
  csr_scan<<<4, 1024>>>(q.cnt, q.off, q.cur);
  csr_fill<<<(EB + 255) / 256, 256>>>(ei_s, ei_t, q.cur, q.lst);

  // embedding GNNs (raw outputs for shat)
  run_gnn_pair(q.xh, q.xl, q.xh + NN * C, q.xl + NN * C,
               WO_EL1, WO_EL2, WO_ERW, WO_EFW, e_rb, e_g, e_b, e_fb,
               q.Hs, q.Ht, nullptr, nullptr, nullptr, nullptr, q);

  shat_kernel<<<dim3(4, 4, BATCH), 256>>>(q.Hs, q.Ht, q.Shat);
  softmax2<<<NN, 128>>>(q.Shat, out, q.S);   // S_0 and first-loop S

  for (int t = 0; t < NSTEPS; t++) {
    unsigned fk0, fk1;
    tf2x32(0u, 42u, 0u, (unsigned)t, fk0, fk1);
    rng_kernel<<<RNG_N / 256, 256>>>(fk0, fk1, q.Rs, q.Rsh, q.Rsl);
    rt_kernel<<<dim3(8, BATCH), 256>>>(q.S, q.Rs, q.Rth, q.Rtl);
    run_gnn_pair(q.Rsh, q.Rsl, q.Rth, q.Rtl,
                 WO_CL1, WO_CL2, WO_CRW, WO_CFW, c_rb, c_g, c_b, c_fb,
                 nullptr, nullptr, q.Osh, q.Osl, q.Oth, q.Otl, q);
    // MLP GEMMs: Am = Os@w1 + b1 (raw) ; BmT = (Ot@w1) transposed in-epilogue
    P6 pm = {};
    for (int z = 0; z < 2; z++) {
      pm.Ahi[z] = z ? q.Oth : q.Osh;
      pm.Alo[z] = z ? q.Otl : q.Osl;
      pm.Ahi2[z] = pm.Ahi[z]; pm.Alo2[z] = pm.Alo[z];
      pm.Bh[z] = q.Wh + WO_MW1; pm.Bl[z] = q.Wl + WO_MW1;
      pm.Craw[z] = z ? q.BmT : q.Am;
      pm.bias[z] = z ? nullptr : m_b1;
      pm.trT[z] = z;
    }
    gemm_bf16<32, 64><<<dim3(HM / 64, NN / 32, 2), 256, smem_b<32, 64>()>>>(pm, HM, C);
    pairwise_sm<<<NN, 128>>>(q.Am, q.BmT, m_w2, m_b2, q.Shat,
                             (t == NSTEPS - 1) ? (out + SB) : q.S);
  }
}

// round 11
// speedup vs baseline: 1.1975x; 1.0447x over previous
#include <cuda_runtime.h>
#include <cuda_bf16.h>
#include <cstdint>

#define NN   1024
#define C    512
#define EB   16384
#define BATCH 8
#define NLOC 128
#define HM   128
#define NSTEPS 10
#define SB   (BATCH*NLOC*NLOC)   /* 131072 */
#define RNG_N (NN*C)             /* 524288 */

// packed-weight word offsets ([K/2][N] uint32 words)
#define WO_EL1 0
#define WO_EL2 131072
#define WO_ERW 262144
#define WO_EFW 393216
#define WO_CL1 655360
#define WO_CL2 786432
#define WO_CRW 917504
#define WO_CFW 1048576
#define WO_MW1 1310720
#define WTOTW  1343488

// ---------------- scratch (no allocation allowed) ----------------
__device__ float g_T[6*NN*C];
__device__ float g_Hs[NN*C], g_Ht[NN*C], g_Rs[NN*C];
__device__ float g_Shat[SB], g_S[SB], g_BmT[SB];
__device__ float g_Am[NN*HM];
__device__ int g_cnt[4*NN], g_off[4*(NN+1)], g_cur[4*NN], g_lst[4*EB];
// packed split weights (bf16x2 words)
__device__ unsigned g_Wh[WTOTW], g_Wl[WTOTW];
// split activations (bf16 hi/lo, natural [row][512] layout)
__device__ __nv_bfloat16 g_xh[2*NN*C], g_xl[2*NN*C];
__device__ __nv_bfloat16 g_Rsh[NN*C], g_Rsl[NN*C], g_Rth[NN*C], g_Rtl[NN*C];
__device__ __nv_bfloat16 g_Hlnh[2*NN*C], g_Hlnl[2*NN*C];
__device__ __nv_bfloat16 g_Osh[NN*C], g_Osl[NN*C], g_Oth[NN*C], g_Otl[NN*C];

// ---------------- threefry-2x32 (matches JAX) ----------------
__host__ __device__ inline void tf2x32(unsigned k0, unsigned k1,
                                       unsigned x0, unsigned x1,
                                       unsigned &o0, unsigned &o1) {
  unsigned ks2 = k0 ^ k1 ^ 0x1BD11BDAu;
  x0 += k0; x1 += k1;
#define TF_ROT(x,r) (((x)<<(r))|((x)>>(32-(r))))
#define TF_RND(r) { x0 += x1; x1 = TF_ROT(x1,(r)); x1 ^= x0; }
  TF_RND(13) TF_RND(15) TF_RND(26) TF_RND(6)
  x0 += k1;  x1 += ks2 + 1u;
  TF_RND(17) TF_RND(29) TF_RND(16) TF_RND(24)
  x0 += ks2; x1 += k0 + 2u;
  TF_RND(13) TF_RND(15) TF_RND(26) TF_RND(6)
  x0 += k0;  x1 += k1 + 3u;
  TF_RND(17) TF_RND(29) TF_RND(16) TF_RND(24)
  x0 += k1;  x1 += ks2 + 4u;
  TF_RND(13) TF_RND(15) TF_RND(26) TF_RND(6)
  x0 += ks2; x1 += k0 + 5u;
  o0 = x0; o1 = x1;
#undef TF_RND
#undef TF_ROT
}

__device__ __forceinline__ void bfsplit(float v, __nv_bfloat16& h, __nv_bfloat16& l) {
  h = __float2bfloat16(v);
  l = __float2bfloat16(v - __bfloat162float(h));
}

// XLA's Giles erfinv + JAX uniform->normal mapping
__device__ __forceinline__ float bits_to_normal(unsigned bits) {
  float f = __uint_as_float((bits >> 9) | 0x3f800000u) - 1.0f;   // [0,1)
  const float LO = -0.99999994f;
  float u = fmaxf(LO, f * 2.0f + LO);
  float w = -log1pf(-u * u);
  float p;
  if (w < 5.0f) {
    w -= 2.5f;
    p = 2.81022636e-08f;
    p = fmaf(p, w, 3.43273939e-07f);
    p = fmaf(p, w, -3.5233877e-06f);
    p = fmaf(p, w, -4.39150654e-06f);
    p = fmaf(p, w, 0.00021858087f);
    p = fmaf(p, w, -0.00125372503f);
    p = fmaf(p, w, -0.00417768164f);
    p = fmaf(p, w, 0.246640727f);
    p = fmaf(p, w, 1.50140941f);
  } else {
    w = sqrtf(w) - 3.0f;
    p = -0.000200214257f;
    p = fmaf(p, w, 0.000100950558f);
    p = fmaf(p, w, 0.00134934322f);
    p = fmaf(p, w, -0.00367342844f);
    p = fmaf(p, w, 0.00573950773f);
    p = fmaf(p, w, -0.0076224613f);
    p = fmaf(p, w, 0.00943887047f);
    p = fmaf(p, w, 1.00167406f);
    p = fmaf(p, w, 2.83297682f);
  }
  return 1.41421356237309504880f * (p * u);
}

// JAX threefry_partitionable: counter (0, i); bits = out0 ^ out1. raw + bf16 split.
__global__ void rng_kernel(unsigned k0, unsigned k1, float* __restrict__ out,
                           __nv_bfloat16* __restrict__ oh, __nv_bfloat16* __restrict__ ol) {
  unsigned i = blockIdx.x * 256u + threadIdx.x;
  unsigned o0, o1;
  tf2x32(k0, k1, 0u, i, o0, o1);
  float v = bits_to_normal(o0 ^ o1);
  out[i] = v;
  __nv_bfloat16 h, l;
  bfsplit(v, h, l);
  oh[i] = h; ol[i] = l;
}

// fp32 -> bf16 hi/lo splitter (activations)
__global__ void split_a(const float* __restrict__ in, __nv_bfloat16* __restrict__ hi,
                        __nv_bfloat16* __restrict__ lo, int n) {
  int i = blockIdx.x * 256 + threadIdx.x;
  if (i >= n) return;
  __nv_bfloat16 h, l;
  bfsplit(in[i], h, l);
  hi[i] = h; lo[i] = l;
}

// weight split+pack: W[K][N] fp32 -> Wh/Wl[K/2][N] bf16x2 words (k pair in one word)
__global__ void split_pack_w(const float* __restrict__ W, unsigned* __restrict__ Wh,
                             unsigned* __restrict__ Wl, int Khalf, int N) {
  int i = blockIdx.x * 256 + threadIdx.x;
  if (i >= Khalf * N) return;
  int j = i / N, n = i % N;
  float v0 = W[(size_t)(2 * j) * N + n];
  float v1 = W[(size_t)(2 * j + 1) * N + n];
  __nv_bfloat16 h0, l0, h1, l1;
  bfsplit(v0, h0, l0);
  bfsplit(v1, h1, l1);
  __nv_bfloat162 ph = __halves2bfloat162(h0, h1);   // low = k even
  __nv_bfloat162 pl = __halves2bfloat162(l0, l1);
  Wh[i] = *reinterpret_cast<unsigned*>(&ph);
  Wl[i] = *reinterpret_cast<unsigned*>(&pl);
}

// ---------------- CSR build ----------------
__global__ void csr_count(const int* __restrict__ eis, const int* __restrict__ eit,
                          int* __restrict__ cnt) {
  int e = blockIdx.x * 256 + threadIdx.x;
  if (e >= EB) return;
  int ss = eis[e], sd = eis[EB + e];
  atomicAdd(&cnt[0 * NN + sd], 1);
  atomicAdd(&cnt[1 * NN + ss], 1);
  int ts = eit[e], td = eit[EB + e];
  atomicAdd(&cnt[2 * NN + td], 1);
  atomicAdd(&cnt[3 * NN + ts], 1);
}

__global__ void csr_scan(const int* __restrict__ cnt, int* __restrict__ off,
                         int* __restrict__ cur) {
  int a = blockIdx.x, t = threadIdx.x;
  __shared__ int sm[NN];
  int v = cnt[a * NN + t];
  sm[t] = v; __syncthreads();
  for (int o = 1; o < NN; o <<= 1) {
    int u = (t >= o) ? sm[t - o] : 0;
    __syncthreads();
    sm[t] += u;
    __syncthreads();
  }
  int excl = sm[t] - v;
  off[a * (NN + 1) + t] = excl;
  cur[a * NN + t] = excl;
  if (t == NN - 1) off[a * (NN + 1) + NN] = sm[t];
}

__global__ void csr_fill(const int* __restrict__ eis, const int* __restrict__ eit,
                         int* __restrict__ cur, int* __restrict__ lst) {
  int e = blockIdx.x * 256 + threadIdx.x;
  if (e >= EB) return;
  int ss = eis[e], sd = eis[EB + e];
  int p = atomicAdd(&cur[0 * NN + sd], 1); lst[0 * EB + p] = ss;
  p = atomicAdd(&cur[1 * NN + ss], 1);     lst[1 * EB + p] = sd;
  int ts = eit[e], td = eit[EB + e];
  p = atomicAdd(&cur[2 * NN + td], 1);     lst[2 * EB + p] = ts;
  p = atomicAdd(&cur[3 * NN + ts], 1);     lst[3 * EB + p] = td;
}

// ---------------- bf16x3 tensor-core GEMM (ldmatrix + 3-stage cp.async) ----------------
struct P6 {
  const __nv_bfloat16* Ahi[6];   // k<512 half, row stride 512
  const __nv_bfloat16* Alo[6];
  const __nv_bfloat16* Ahi2[6];  // k>=512 (virtual concat)
  const __nv_bfloat16* Alo2[6];
  const unsigned* Bh[6];         // packed [K/2][N] words
  const unsigned* Bl[6];
  float*          Craw[6];       // nullable
  __nv_bfloat16*  Chi[6];        // nullable split epilogue
  __nv_bfloat16*  Clo[6];
  const float*    bias[6];
  int trT[6];                    // store Craw transposed [b][h][j] (Nn must be 128)
};

__device__ __forceinline__ void mma16(float* d, const unsigned* a, const unsigned* b) {
  asm volatile(
    "mma.sync.aligned.m16n8k16.row.col.f32.bf16.bf16.f32 "
    "{%0,%1,%2,%3}, {%4,%5,%6,%7}, {%8,%9}, {%0,%1,%2,%3};\n"
    : "+f"(d[0]), "+f"(d[1]), "+f"(d[2]), "+f"(d[3])
    : "r"(a[0]), "r"(a[1]), "r"(a[2]), "r"(a[3]), "r"(b[0]), "r"(b[1]));
}

__device__ __forceinline__ void ldsm4(unsigned* r, unsigned addr) {
  asm volatile("ldmatrix.sync.aligned.m8n8.x4.shared.b16 {%0,%1,%2,%3}, [%4];"
    : "=r"(r[0]), "=r"(r[1]), "=r"(r[2]), "=r"(r[3]) : "r"(addr));
}

__device__ __forceinline__ void cpa16(unsigned dst, const void* src) {
  asm volatile("cp.async.cg.shared.global [%0], [%1], 16;" :: "r"(dst), "l"(src));
}
__device__ __forceinline__ void cp_commit() { asm volatile("cp.async.commit_group;"); }

// 3-stage smem: A[3buf][2hl][BM][12w] + B[3buf][2hl][8][BN+8]
template<int BM, int BN>
constexpr int smem_b() { return (3 * 2 * BM * 12 + 3 * 2 * 8 * (BN + 8)) * 4; }

// BK=16. A fragments via ldmatrix.x4 from [m][kpair] rows (pitch 12 words, conflict-free);
// B fragments scalar LDS from [kpair][n] rows (pitch BN+8, conflict-free).
template<int BM, int BN>
__global__ __launch_bounds__(256) void gemm_bf16(P6 p, int Nn, int K) {
  constexpr int AP = 12, BP = BN + 8;
  constexpr int NAOP = 2 * BM * 2;          // 16B ops per A tile
  constexpr int NBOP = 2 * 8 * (BN / 4);    // 16B ops per B tile
  constexpr int WM = BM / 2, WN = BN / 4;
  constexpr int MI = WM / 16, NI = WN / 8;

  const int tid = threadIdx.x;
  const int z = blockIdx.z;
  const __nv_bfloat16* __restrict__ Ahi = p.Ahi[z];
  const __nv_bfloat16* __restrict__ Alo = p.Alo[z];
  const __nv_bfloat16* __restrict__ Ahi2 = p.Ahi2[z];
  const __nv_bfloat16* __restrict__ Alo2 = p.Alo2[z];
  const unsigned* __restrict__ Bh = p.Bh[z];
  const unsigned* __restrict__ Bl = p.Bl[z];
  float* __restrict__ Craw = p.Craw[z];
  __nv_bfloat16* __restrict__ Chi = p.Chi[z];
  __nv_bfloat16* __restrict__ Clo = p.Clo[z];
  const float* __restrict__ bias = p.bias[z];
  const int trT = p.trT[z];
  const int row0 = blockIdx.y * BM, col0 = blockIdx.x * BN;

  extern __shared__ unsigned smem_u[];
  unsigned* As = smem_u;
  unsigned* Bs = smem_u + 3 * 2 * BM * AP;
  const unsigned as_u = (unsigned)__cvta_generic_to_shared(As);
  const unsigned bs_u = (unsigned)__cvta_generic_to_shared(Bs);

  const int lane = tid & 31;
  const int wid = tid >> 5;
  const int gid = lane >> 2, tg = lane & 3;
  const int wr = wid >> 2, wc = wid & 3;   // 2 x 4 warps

  float acc[MI][NI][4];
#pragma unroll
  for (int i = 0; i < MI; i++)
#pragma unroll
    for (int j = 0; j < NI; j++)
#pragma unroll
      for (int q = 0; q < 4; q++) acc[i][j][q] = 0.f;

  const int nk = K >> 4;

  auto ldg = [&](int kt, int buf) {
    const __nv_bfloat16* Ah = (kt >= 512) ? Ahi2 : Ahi;
    const __nv_bfloat16* Al = (kt >= 512) ? Alo2 : Alo;
    int ko = kt & 511;
    int ktp = kt >> 1;
#pragma unroll
    for (int i = 0; i < (NAOP + 255) / 256; i++) {
      int idx = tid + i * 256;
      if (NAOP < 256 || NAOP % 256) { if (idx >= NAOP) break; }
      int hl = idx / (BM * 2);
      int rem = idx - hl * (BM * 2);
      int m = rem >> 1, ch = rem & 1;
      const __nv_bfloat16* src = (hl ? Al : Ah) + (size_t)(row0 + m) * 512 + ko + ch * 8;
      unsigned dst = as_u + (unsigned)((((buf * 2 + hl) * BM + m) * AP + ch * 4) * 4);
      cpa16(dst, src);
    }
#pragma unroll
    for (int i = 0; i < (NBOP + 255) / 256; i++) {
      int idx = tid + i * 256;
      if (NBOP < 256 || NBOP % 256) { if (idx >= NBOP) break; }
      int hl = idx / (8 * (BN / 4));
      int rem = idx - hl * (8 * (BN / 4));
      int kp = rem / (BN / 4), n4 = rem % (BN / 4);
      const unsigned* src = (hl ? Bl : Bh) + (size_t)(ktp + kp) * Nn + col0 + n4 * 4;
      unsigned dst = bs_u + (unsigned)((((buf * 2 + hl) * 8 + kp) * BP + n4 * 4) * 4);
      cpa16(dst, src);
    }
  };

  // ldmatrix lane mapping: row = warp_m0 + (lane&15), koff words = (lane&16)?4:0
  const int lrow = lane & 15;
  const int lko = (lane & 16) ? 4 : 0;

  auto compute = [&](int buf) {
    const unsigned* B0 = Bs + (size_t)((buf * 2 + 0) * 8) * BP;
    const unsigned* B1 = Bs + (size_t)((buf * 2 + 1) * 8) * BP;
    unsigned ah[MI][4], al[MI][4], bh[NI][2], bl[NI][2];
#pragma unroll
    for (int mi = 0; mi < MI; mi++) {
      int m = wr * WM + mi * 16 + lrow;
      ldsm4(ah[mi], as_u + (unsigned)((((buf * 2 + 0) * BM + m) * AP + lko) * 4));
      ldsm4(al[mi], as_u + (unsigned)((((buf * 2 + 1) * BM + m) * AP + lko) * 4));
    }
#pragma unroll
    for (int ni = 0; ni < NI; ni++) {
      int n = wc * WN + ni * 8 + gid;
      bh[ni][0] = B0[tg * BP + n];
      bh[ni][1] = B0[(tg + 4) * BP + n];
      bl[ni][0] = B1[tg * BP + n];
      bl[ni][1] = B1[(tg + 4) * BP + n];
    }
#pragma unroll
    for (int mi = 0; mi < MI; mi++)
#pragma unroll
      for (int ni = 0; ni < NI; ni++) {
        mma16(acc[mi][ni], ah[mi], bl[ni]);
        mma16(acc[mi][ni], al[mi], bh[ni]);
        mma16(acc[mi][ni], ah[mi], bh[ni]);
      }
  };

  // 3-stage pipeline: one __syncthreads per k-tile
  ldg(0, 0);
  cp_commit();
  if (nk > 1) { ldg(16, 1); cp_commit(); }
  for (int t = 0; t < nk; t++) {
    int buf = t % 3;
    if (t + 1 < nk) {
      asm volatile("cp.async.wait_group 1;");   // tile t complete, t+1 may fly
    } else {
      asm volatile("cp.async.wait_group 0;");
    }
    __syncthreads();
    if (t + 2 < nk) {
      ldg((t + 2) << 4, (t + 2) % 3);
      cp_commit();
    }
    compute(buf);
  }

#pragma unroll
  for (int mi = 0; mi < MI; mi++) {
#pragma unroll
    for (int ni = 0; ni < NI; ni++) {
      int r = row0 + wr * WM + mi * 16 + gid;
      int c = col0 + wc * WN + ni * 8 + tg * 2;
      float b0 = bias ? bias[c] : 0.f;
      float b1 = bias ? bias[c + 1] : 0.f;
      float v[4] = {acc[mi][ni][0] + b0, acc[mi][ni][1] + b1,
                    acc[mi][ni][2] + b0, acc[mi][ni][3] + b1};
      if (Craw) {
        if (trT) {
          int b_ = r >> 7, j_ = r & 127;
          int b2_ = (r + 8) >> 7, j2_ = (r + 8) & 127;
          Craw[(size_t)b_ * 16384 + (c) * 128 + j_]       = v[0];
          Craw[(size_t)b_ * 16384 + (c + 1) * 128 + j_]   = v[1];
          Craw[(size_t)b2_ * 16384 + (c) * 128 + j2_]     = v[2];
          Craw[(size_t)b2_ * 16384 + (c + 1) * 128 + j2_] = v[3];
        } else {
          size_t i0 = (size_t)r * Nn + c, i1 = (size_t)(r + 8) * Nn + c;
          Craw[i0] = v[0]; Craw[i0 + 1] = v[1];
          Craw[i1] = v[2]; Craw[i1 + 1] = v[3];
        }
      }
      if (Chi) {
        size_t i0 = (size_t)r * Nn + c, i1 = (size_t)(r + 8) * Nn + c;
        __nv_bfloat16 h, l;
        bfsplit(v[0], h, l); Chi[i0] = h;     Clo[i0] = l;
        bfsplit(v[1], h, l); Chi[i0 + 1] = h; Clo[i0 + 1] = l;
        bfsplit(v[2], h, l); Chi[i1] = h;     Clo[i1] = l;
        bfsplit(v[3], h, l); Chi[i1 + 1] = h; Clo[i1 + 1] = l;
      }
    }
  }
}

// ---------------- fused edge-mean + ReLU + LayerNorm (both sides), bf16-split out ----------------
__global__ __launch_bounds__(256)
void agg_ln(const float* __restrict__ T, const int* __restrict__ off,
            const int* __restrict__ lst,
            const float* __restrict__ gamma, const float* __restrict__ beta,
            __nv_bfloat16* __restrict__ Hhi, __nv_bfloat16* __restrict__ Hlo) {
  int n = blockIdx.x, side = blockIdx.y, t = threadIdx.x;
  const float* T1 = T + (size_t)(side * 3 + 0) * NN * C;
  const float* T2 = T + (size_t)(side * 3 + 1) * NN * C;
  const float* TR = T + (size_t)(side * 3 + 2) * NN * C;
  const int* inoff = off + (side * 2 + 0) * (NN + 1);
  const int* outoff = off + (side * 2 + 1) * (NN + 1);
  const int* inlst = lst + (size_t)(side * 2 + 0) * EB;
  const int* outlst = lst + (size_t)(side * 2 + 1) * EB;
  int c0 = t, c1 = t + 256;
  float a0 = TR[n * C + c0], a1 = TR[n * C + c1];
  {
    int s = inoff[n], e = inoff[n + 1];
    float s0 = 0.f, s1 = 0.f;
    for (int j = s; j < e; j++) {
      int m = inlst[j];
      s0 += T1[m * C + c0];
      s1 += T1[m * C + c1];
    }
    float inv = 1.0f / (float)max(e - s, 1);
    a0 += s0 * inv; a1 += s1 * inv;
  }
  {
    int s = outoff[n], e = outoff[n + 1];
    float s0 = 0.f, s1 = 0.f;
    for (int j = s; j < e; j++) {
      int m = outlst[j];
      s0 += T2[m * C + c0];
      s1 += T2[m * C + c1];
    }
    float inv = 1.0f / (float)max(e - s, 1);
    a0 += s0 * inv; a1 += s1 * inv;
  }
  a0 = fmaxf(a0, 0.f); a1 = fmaxf(a1, 0.f);
  __shared__ float red[256];
  __shared__ float mu_s, rstd_s;
  red[t] = a0 + a1; __syncthreads();
  for (int o = 128; o > 0; o >>= 1) { if (t < o) red[t] += red[t + o]; __syncthreads(); }
  if (t == 0) mu_s = red[0] * (1.0f / C);
  __syncthreads();
  float mu = mu_s;
  float d0 = a0 - mu, d1 = a1 - mu;
  __syncthreads();
  red[t] = d0 * d0 + d1 * d1; __syncthreads();
  for (int o = 128; o > 0; o >>= 1) { if (t < o) red[t] += red[t + o]; __syncthreads(); }
  if (t == 0) rstd_s = rsqrtf(red[0] * (1.0f / C) + 1e-5f);
  __syncthreads();
  float rstd = rstd_s;
  float v0 = d0 * rstd * gamma[c0] + beta[c0];
  float v1 = d1 * rstd * gamma[c1] + beta[c1];
  size_t base = (size_t)(side * NN + n) * C;
  __nv_bfloat16 h, l;
  bfsplit(v0, h, l); Hhi[base + c0] = h; Hlo[base + c0] = l;
  bfsplit(v1, h, l); Hhi[base + c1] = h; Hlo[base + c1] = l;
}

// ---------------- S_hat = Hs_b @ Ht_b^T ----------------
__global__ __launch_bounds__(256)
void shat_kernel(const float* __restrict__ Hs, const float* __restrict__ Ht,
                 float* __restrict__ Shat) {
  int b = blockIdx.z, s0 = blockIdx.y * 32, t0 = blockIdx.x * 32;
  int tid = threadIdx.x, tx = tid & 15, ty = tid >> 4;
  __shared__ float sA[32][33], sBt[32][33];
  float acc[2][2] = {};
  for (int k0 = 0; k0 < C; k0 += 32) {
#pragma unroll
    for (int l = 0; l < 4; l++) {
      int idx = tid + l * 256;
      int r = idx >> 5, k = idx & 31;
      sA[r][k] = Hs[(b * NLOC + s0 + r) * C + k0 + k];
      sBt[r][k] = Ht[(b * NLOC + t0 + r) * C + k0 + k];
    }
    __syncthreads();
#pragma unroll
    for (int k = 0; k < 32; k++) {
      float a0 = sA[ty * 2][k], a1 = sA[ty * 2 + 1][k];
      float b0 = sBt[tx * 2][k], b1 = sBt[tx * 2 + 1][k];
      acc[0][0] = fmaf(a0, b0, acc[0][0]);
      acc[0][1] = fmaf(a0, b1, acc[0][1]);
      acc[1][0] = fmaf(a1, b0, acc[1][0]);
      acc[1][1] = fmaf(a1, b1, acc[1][1]);
    }
    __syncthreads();
  }
#pragma unroll
  for (int i = 0; i < 2; i++)
#pragma unroll
    for (int j = 0; j < 2; j++)
      Shat[b * (NLOC * NLOC) + (s0 + ty * 2 + i) * NLOC + (t0 + tx * 2 + j)] = acc[i][j];
}

// ---------------- row softmax, dual output ----------------
__global__ void softmax2(const float* __restrict__ in, float* __restrict__ o1,
                         float* __restrict__ o2) {
  int row = blockIdx.x, t = threadIdx.x;
  __shared__ float red[128];
  float v = in[row * 128 + t];
  red[t] = v; __syncthreads();
  for (int o = 64; o > 0; o >>= 1) { if (t < o) red[t] = fmaxf(red[t], red[t + o]); __syncthreads(); }
  float mx = red[0]; __syncthreads();
  float e = expf(v - mx);
  red[t] = e; __syncthreads();
  for (int o = 64; o > 0; o >>= 1) { if (t < o) red[t] += red[t + o]; __syncthreads(); }
  float r = e / red[0];
  o1[row * 128 + t] = r;
  o2[row * 128 + t] = r;
}

// ---------------- R_t = S^T @ R_s, bf16-split output ----------------
__global__ __launch_bounds__(256)
void rt_kernel(const float* __restrict__ S, const float* __restrict__ Rs,
               __nv_bfloat16* __restrict__ Rthi, __nv_bfloat16* __restrict__ Rtlo) {
  int b = blockIdx.y, t0 = blockIdx.x * 16;
  int tid = threadIdx.x;
  __shared__ float sS[128][16];
#pragma unroll
  for (int l = 0; l < 8; l++) {
    int idx = tid + l * 256;
    int s = idx >> 4, tt = idx & 15;
    sS[s][tt] = S[b * (NLOC * NLOC) + s * NLOC + t0 + tt];
  }
  __syncthreads();
  int c = tid;
  float acc0[16] = {}, acc1[16] = {};
  for (int s = 0; s < NLOC; s++) {
    float r0 = Rs[(b * NLOC + s) * C + c];
    float r1 = Rs[(b * NLOC + s) * C + c + 256];
#pragma unroll
    for (int tt = 0; tt < 16; tt++) {
      float sv = sS[s][tt];
      acc0[tt] = fmaf(sv, r0, acc0[tt]);
      acc1[tt] = fmaf(sv, r1, acc1[tt]);
    }
  }
#pragma unroll
  for (int tt = 0; tt < 16; tt++) {
    size_t i0 = (size_t)(b * NLOC + t0 + tt) * C + c;
    __nv_bfloat16 h, l;
    bfsplit(acc0[tt], h, l); Rthi[i0] = h;       Rtlo[i0] = l;
    bfsplit(acc1[tt], h, l); Rthi[i0 + 256] = h; Rtlo[i0 + 256] = l;
  }
}

// ---------------- fused: S_hat += MLP pairwise; S_next = softmax(row) ----------------
__global__ void pairwise_sm(const float* __restrict__ A, const float* __restrict__ BmT,
                            const float* __restrict__ w2, const float* __restrict__ b2,
                            float* __restrict__ Shat, float* __restrict__ Sout) {
  int bi = blockIdx.x;
  int b = bi >> 7, j = threadIdx.x;
  __shared__ float sA[128], sw[128], red[128];
  sA[j] = A[bi * HM + j];
  sw[j] = w2[j];
  __syncthreads();
  float acc = 0.f;
  const float* Bp = BmT + b * (HM * NLOC) + j;
#pragma unroll 8
  for (int h = 0; h < HM; h++) {
    float d = sA[h] - Bp[h * NLOC];
    acc = fmaf(fmaxf(d, 0.f), sw[h], acc);
  }
  float val = Shat[bi * NLOC + j] + acc + b2[0];
  Shat[bi * NLOC + j] = val;
  red[j] = val; __syncthreads();
  for (int o = 64; o > 0; o >>= 1) { if (j < o) red[j] = fmaxf(red[j], red[j + o]); __syncthreads(); }
  float mx = red[0]; __syncthreads();
  float e = expf(val - mx);
  red[j] = e; __syncthreads();
  for (int o = 64; o > 0; o >>= 1) { if (j < o) red[j] += red[j + o]; __syncthreads(); }
  Sout[bi * NLOC + j] = e / red[0];
}

// ---------------- host side ----------------
struct Ptrs {
  float *T, *Hs, *Ht, *Rs, *Shat, *S, *BmT, *Am;
  unsigned *Wh, *Wl;
  __nv_bfloat16 *xh, *xl, *Rsh, *Rsl, *Rth, *Rtl, *Hlnh, *Hlnl, *Osh, *Osl, *Oth, *Otl;
  int *cnt, *off, *cur, *lst;
};

static void run_gnn_pair(const __nv_bfloat16* ah_s, const __nv_bfloat16* al_s,
                         const __nv_bfloat16* ah_t, const __nv_bfloat16* al_t,
                         size_t oL1, size_t oL2, size_t oRW, size_t oFW,
                         const float* rb, const float* g, const float* b,
                         const float* Fb,
                         float* rawS, float* rawT,
                         __nv_bfloat16* hiS, __nv_bfloat16* loS,
                         __nv_bfloat16* hiT, __nv_bfloat16* loT,
                         const Ptrs& q) {
  P6 p3 = {};
  for (int z = 0; z < 6; z++) {
    int side = z / 3, w = z % 3;
    p3.Ahi[z] = side ? ah_t : ah_s;
    p3.Alo[z] = side ? al_t : al_s;
    p3.Ahi2[z] = p3.Ahi[z]; p3.Alo2[z] = p3.Alo[z];
    size_t wo = (w == 0) ? oL1 : (w == 1) ? oL2 : oRW;
    p3.Bh[z] = q.Wh + wo; p3.Bl[z] = q.Wl + wo;
    p3.Craw[z] = q.T + (size_t)z * NN * C;
    p3.bias[z] = (w == 2) ? rb : nullptr;
  }
  gemm_bf16<128, 128><<<dim3(C / 128, NN / 128, 6), 256, smem_b<128, 128>()>>>(p3, C, C);

  agg_ln<<<dim3(NN, 2), 256>>>(q.T, q.off, q.lst, g, b, q.Hlnh, q.Hlnl);

  // virtual-concat GEMM: [x|H] @ Fw (K=1024)
  P6 pc = {};
  for (int z = 0; z < 2; z++) {
    pc.Ahi[z] = z ? ah_t : ah_s;
    pc.Alo[z] = z ? al_t : al_s;
    pc.Ahi2[z] = q.Hlnh + (size_t)z * NN * C;
    pc.Alo2[z] = q.Hlnl + (size_t)z * NN * C;
    pc.Bh[z] = q.Wh + oFW; pc.Bl[z] = q.Wl + oFW;
    pc.Craw[z] = z ? rawT : rawS;
    pc.Chi[z] = z ? hiT : hiS;
    pc.Clo[z] = z ? loT : loS;
    pc.bias[z] = Fb;
  }
  gemm_bf16<64, 128><<<dim3(C / 128, NN / 64, 2), 256, smem_b<64, 128>()>>>(pc, C, 2 * C);
}

extern "C" void kernel_launch(void* const* d_in, const int* in_sizes, int n_in,
                              void* d_out, int out_size) {
  const float* x_s  = (const float*)d_in[0];
  const int*   ei_s = (const int*)d_in[1];
  const float* x_t  = (const float*)d_in[4];
  const int*   ei_t = (const int*)d_in[5];
  const float* e_lin1 = (const float*)d_in[8];
  const float* e_lin2 = (const float*)d_in[9];
  const float* e_rw   = (const float*)d_in[10];
  const float* e_rb   = (const float*)d_in[11];
  const float* e_g    = (const float*)d_in[12];
  const float* e_b    = (const float*)d_in[13];
  const float* e_fw   = (const float*)d_in[14];
  const float* e_fb   = (const float*)d_in[15];
  const float* c_lin1 = (const float*)d_in[16];
  const float* c_lin2 = (const float*)d_in[17];
  const float* c_rw   = (const float*)d_in[18];
  const float* c_rb   = (const float*)d_in[19];
  const float* c_g    = (const float*)d_in[20];
  const float* c_b    = (const float*)d_in[21];
  const float* c_fw   = (const float*)d_in[22];
  const float* c_fb   = (const float*)d_in[23];
  const float* m_w1   = (const float*)d_in[24];
  const float* m_b1   = (const float*)d_in[25];
  const float* m_w2   = (const float*)d_in[26];
  const float* m_b2   = (const float*)d_in[27];
  float* out = (float*)d_out;

  Ptrs q;
  cudaGetSymbolAddress((void**)&q.T,    g_T);
  cudaGetSymbolAddress((void**)&q.Hs,   g_Hs);
  cudaGetSymbolAddress((void**)&q.Ht,   g_Ht);
  cudaGetSymbolAddress((void**)&q.Rs,   g_Rs);
  cudaGetSymbolAddress((void**)&q.Shat, g_Shat);
  cudaGetSymbolAddress((void**)&q.S,    g_S);
  cudaGetSymbolAddress((void**)&q.BmT,  g_BmT);
  cudaGetSymbolAddress((void**)&q.Am,   g_Am);
  cudaGetSymbolAddress((void**)&q.Wh,   g_Wh);
  cudaGetSymbolAddress((void**)&q.Wl,   g_Wl);
  cudaGetSymbolAddress((void**)&q.xh,   g_xh);
  cudaGetSymbolAddress((void**)&q.xl,   g_xl);
  cudaGetSymbolAddress((void**)&q.Rsh,  g_Rsh);
  cudaGetSymbolAddress((void**)&q.Rsl,  g_Rsl);
  cudaGetSymbolAddress((void**)&q.Rth,  g_Rth);
  cudaGetSymbolAddress((void**)&q.Rtl,  g_Rtl);
  cudaGetSymbolAddress((void**)&q.Hlnh, g_Hlnh);
  cudaGetSymbolAddress((void**)&q.Hlnl, g_Hlnl);
  cudaGetSymbolAddress((void**)&q.Osh,  g_Osh);
  cudaGetSymbolAddress((void**)&q.Osl,  g_Osl);
  cudaGetSymbolAddress((void**)&q.Oth,  g_Oth);
  cudaGetSymbolAddress((void**)&q.Otl,  g_Otl);
  cudaGetSymbolAddress((void**)&q.cnt,  g_cnt);
  cudaGetSymbolAddress((void**)&q.off,  g_off);
  cudaGetSymbolAddress((void**)&q.cur,  g_cur);
  cudaGetSymbolAddress((void**)&q.lst,  g_lst);

  cudaFuncSetAttribute(gemm_bf16<128, 128>, cudaFuncAttributeMaxDynamicSharedMemorySize, smem_b<128, 128>());
  cudaFuncSetAttribute(gemm_bf16<64, 128>,  cudaFuncAttributeMaxDynamicSharedMemorySize, smem_b<64, 128>());
  cudaFuncSetAttribute(gemm_bf16<32, 64>,   cudaFuncAttributeMaxDynamicSharedMemorySize, smem_b<32, 64>());

  // weight split+pack (once per call)
  struct { const float* src; size_t woff; int kh, n; } wj[9] = {
    {e_lin1, WO_EL1, C / 2, C}, {e_lin2, WO_EL2, C / 2, C}, {e_rw, WO_ERW, C / 2, C},
    {e_fw, WO_EFW, C, C},
    {c_lin1, WO_CL1, C / 2, C}, {c_lin2, WO_CL2, C / 2, C}, {c_rw, WO_CRW, C / 2, C},
    {c_fw, WO_CFW, C, C},
    {m_w1, WO_MW1, C / 2, HM},
  };
  for (int i = 0; i < 9; i++) {
    int n = wj[i].kh * wj[i].n;
    split_pack_w<<<(n + 255) / 256, 256>>>(wj[i].src, q.Wh + wj[i].woff,
                                           q.Wl + wj[i].woff, wj[i].kh, wj[i].n);
  }
  split_a<<<NN * C / 256, 256>>>(x_s, q.xh, q.xl, NN * C);
  split_a<<<NN * C / 256, 256>>>(x_t, q.xh + NN * C, q.xl + NN * C, NN * C);

  // CSR build
  cudaMemsetAsync(q.cnt, 0, 4 * NN * sizeof(int));
  csr_count<<<(EB + 255) / 256, 256>>>(ei_s, ei_t, q.cnt);
  csr_scan<<<4, 1024>>>(q.cnt, q.off, q.cur);
  csr_fill<<<(EB + 255) / 256, 256>>>(ei_s, ei_t, q.cur, q.lst);

  // embedding GNNs (raw outputs for shat)
  run_gnn_pair(q.xh, q.xl, q.xh + NN * C, q.xl + NN * C,
               WO_EL1, WO_EL2, WO_ERW, WO_EFW, e_rb, e_g, e_b, e_fb,
               q.Hs, q.Ht, nullptr, nullptr, nullptr, nullptr, q);

  shat_kernel<<<dim3(4, 4, BATCH), 256>>>(q.Hs, q.Ht, q.Shat);
  softmax2<<<NN, 128>>>(q.Shat, out, q.S);   // S_0 and first-loop S

  for (int t = 0; t < NSTEPS; t++) {
    unsigned fk0, fk1;
    tf2x32(0u, 42u, 0u, (unsigned)t, fk0, fk1);
    rng_kernel<<<RNG_N / 256, 256>>>(fk0, fk1, q.Rs, q.Rsh, q.Rsl);
    rt_kernel<<<dim3(8, BATCH), 256>>>(q.S, q.Rs, q.Rth, q.Rtl);
    run_gnn_pair(q.Rsh, q.Rsl, q.Rth, q.Rtl,
                 WO_CL1, WO_CL2, WO_CRW, WO_CFW, c_rb, c_g, c_b, c_fb,
                 nullptr, nullptr, q.Osh, q.Osl, q.Oth, q.Otl, q);
    // MLP GEMMs: Am = Os@w1 + b1 (raw) ; BmT = (Ot@w1) transposed in-epilogue
    P6 pm = {};
    for (int z = 0; z < 2; z++) {
      pm.Ahi[z] = z ? q.Oth : q.Osh;
      pm.Alo[z] = z ? q.Otl : q.Osl;
      pm.Ahi2[z] = pm.Ahi[z]; pm.Alo2[z] = pm.Alo[z];
      pm.Bh[z] = q.Wh + WO_MW1; pm.Bl[z] = q.Wl + WO_MW1;
      pm.Craw[z] = z ? q.BmT : q.Am;
      pm.bias[z] = z ? nullptr : m_b1;
      pm.trT[z] = z;
    }
    gemm_bf16<32, 64><<<dim3(HM / 64, NN / 32, 2), 256, smem_b<32, 64>()>>>(pm, HM, C);
    pairwise_sm<<<NN, 128>>>(q.Am, q.BmT, m_w2, m_b2, q.Shat,
                             (t == NSTEPS - 1) ? (out + SB) : q.S);
  }
}

// round 15
// speedup vs baseline: 1.4401x; 1.2026x over previous
#include <cuda_runtime.h>
#include <cuda_bf16.h>
#include <cstdint>

#define NN   1024
#define C    512
#define EB   16384
#define BATCH 8
#define NLOC 128
#define HM   128
#define NSTEPS 10
#define SB   (BATCH*NLOC*NLOC)   /* 131072 */
#define RNG_N (NN*C)             /* 524288 */

// packed-weight word offsets ([K/2][N] uint32 words)
#define WO_EL1 0
#define WO_EL2 131072
#define WO_ERW 262144
#define WO_EFW 393216
#define WO_CL1 655360
#define WO_CL2 786432
#define WO_CRW 917504
#define WO_CFW 1048576
#define WO_MW1 1310720
#define WO_WA  1343488            /* combined c_fw@m_w1: K=1024,N=128 -> 65536 words */
#define WTOTW  1409024

// ---------------- scratch (no allocation allowed) ----------------
__device__ float g_T[6*NN*C];
__device__ float g_Hs[NN*C], g_Ht[NN*C], g_Rs[NN*C];
__device__ float g_Shat[SB], g_S[SB], g_BmT[SB];
__device__ float g_Am[NN*HM];
__device__ float g_Wa[NN*HM];           // c_fw@m_w1 fp32 (1024x128)
__device__ float g_biasA[2*HM];         // [0:128) s-side (+m_b1), [128:256) t-side
__device__ int g_cnt[4*NN], g_off[4*(NN+1)], g_cur[4*NN], g_lst[4*EB];
// packed split weights (bf16x2 words)
__device__ unsigned g_Wh[WTOTW], g_Wl[WTOTW];
// split activations (bf16 hi/lo, natural [row][512] layout)
__device__ __nv_bfloat16 g_xh[2*NN*C], g_xl[2*NN*C];
__device__ __nv_bfloat16 g_Rsh[NN*C], g_Rsl[NN*C], g_Rth[NN*C], g_Rtl[NN*C];
__device__ __nv_bfloat16 g_Hlnh[2*NN*C], g_Hlnl[2*NN*C];

// ---------------- threefry-2x32 (matches JAX) ----------------
__host__ __device__ inline void tf2x32(unsigned k0, unsigned k1,
                                       unsigned x0, unsigned x1,
                                       unsigned &o0, unsigned &o1) {
  unsigned ks2 = k0 ^ k1 ^ 0x1BD11BDAu;
  x0 += k0; x1 += k1;
#define TF_ROT(x,r) (((x)<<(r))|((x)>>(32-(r))))
#define TF_RND(r) { x0 += x1; x1 = TF_ROT(x1,(r)); x1 ^= x0; }
  TF_RND(13) TF_RND(15) TF_RND(26) TF_RND(6)
  x0 += k1;  x1 += ks2 + 1u;
  TF_RND(17) TF_RND(29) TF_RND(16) TF_RND(24)
  x0 += ks2; x1 += k0 + 2u;
  TF_RND(13) TF_RND(15) TF_RND(26) TF_RND(6)
  x0 += k0;  x1 += k1 + 3u;
  TF_RND(17) TF_RND(29) TF_RND(16) TF_RND(24)
  x0 += k1;  x1 += ks2 + 4u;
  TF_RND(13) TF_RND(15) TF_RND(26) TF_RND(6)
  x0 += ks2; x1 += k0 + 5u;
  o0 = x0; o1 = x1;
#undef TF_RND
#undef TF_ROT
}

__device__ __forceinline__ void bfsplit(float v, __nv_bfloat16& h, __nv_bfloat16& l) {
  h = __float2bfloat16(v);
  l = __float2bfloat16(v - __bfloat162float(h));
}

// XLA's Giles erfinv + JAX uniform->normal mapping
__device__ __forceinline__ float bits_to_normal(unsigned bits) {
  float f = __uint_as_float((bits >> 9) | 0x3f800000u) - 1.0f;   // [0,1)
  const float LO = -0.99999994f;
  float u = fmaxf(LO, f * 2.0f + LO);
  float w = -log1pf(-u * u);
  float p;
  if (w < 5.0f) {
    w -= 2.5f;
    p = 2.81022636e-08f;
    p = fmaf(p, w, 3.43273939e-07f);
    p = fmaf(p, w, -3.5233877e-06f);
    p = fmaf(p, w, -4.39150654e-06f);
    p = fmaf(p, w, 0.00021858087f);
    p = fmaf(p, w, -0.00125372503f);
    p = fmaf(p, w, -0.00417768164f);
    p = fmaf(p, w, 0.246640727f);
    p = fmaf(p, w, 1.50140941f);
  } else {
    w = sqrtf(w) - 3.0f;
    p = -0.000200214257f;
    p = fmaf(p, w, 0.000100950558f);
    p = fmaf(p, w, 0.00134934322f);
    p = fmaf(p, w, -0.00367342844f);
    p = fmaf(p, w, 0.00573950773f);
    p = fmaf(p, w, -0.0076224613f);
    p = fmaf(p, w, 0.00943887047f);
    p = fmaf(p, w, 1.00167406f);
    p = fmaf(p, w, 2.83297682f);
  }
  return 1.41421356237309504880f * (p * u);
}

// JAX threefry_partitionable: counter (0, i); bits = out0 ^ out1. raw + bf16 split.
__global__ void rng_kernel(unsigned k0, unsigned k1, float* __restrict__ out,
                           __nv_bfloat16* __restrict__ oh, __nv_bfloat16* __restrict__ ol) {
  unsigned i = blockIdx.x * 256u + threadIdx.x;
  unsigned o0, o1;
  tf2x32(k0, k1, 0u, i, o0, o1);
  float v = bits_to_normal(o0 ^ o1);
  out[i] = v;
  __nv_bfloat16 h, l;
  bfsplit(v, h, l);
  oh[i] = h; ol[i] = l;
}

// fp32 -> bf16 hi/lo splitter (activations)
__global__ void split_a(const float* __restrict__ in, __nv_bfloat16* __restrict__ hi,
                        __nv_bfloat16* __restrict__ lo, int n) {
  int i = blockIdx.x * 256 + threadIdx.x;
  if (i >= n) return;
  __nv_bfloat16 h, l;
  bfsplit(in[i], h, l);
  hi[i] = h; lo[i] = l;
}

// weight split+pack: W[K][N] fp32 -> Wh/Wl[K/2][N] bf16x2 words (k pair in one word)
__global__ void split_pack_w(const float* __restrict__ W, unsigned* __restrict__ Wh,
                             unsigned* __restrict__ Wl, int Khalf, int N) {
  int i = blockIdx.x * 256 + threadIdx.x;
  if (i >= Khalf * N) return;
  int j = i / N, n = i % N;
  float v0 = W[(size_t)(2 * j) * N + n];
  float v1 = W[(size_t)(2 * j + 1) * N + n];
  __nv_bfloat16 h0, l0, h1, l1;
  bfsplit(v0, h0, l0);
  bfsplit(v1, h1, l1);
  __nv_bfloat162 ph = __halves2bfloat162(h0, h1);   // low = k even
  __nv_bfloat162 pl = __halves2bfloat162(l0, l1);
  Wh[i] = *reinterpret_cast<unsigned*>(&ph);
  Wl[i] = *reinterpret_cast<unsigned*>(&pl);
}

// combined weight: Wa = c_fw @ m_w1 (fp32), biasA = {c_fb@m_w1 + m_b1, c_fb@m_w1}
__global__ void combine_w(const float* __restrict__ cfw, const float* __restrict__ mw1,
                          const float* __restrict__ cfb, const float* __restrict__ mb1,
                          float* __restrict__ Wa, float* __restrict__ biasA) {
  int k = blockIdx.x, h = threadIdx.x;   // grid 1025, block 128
  if (k < NN) {
    float acc = 0.f;
    for (int j = 0; j < C; j++)
      acc = fmaf(cfw[(size_t)k * C + j], mw1[(size_t)j * HM + h], acc);
    Wa[(size_t)k * HM + h] = acc;
  } else {
    float acc = 0.f;
    for (int j = 0; j < C; j++)
      acc = fmaf(cfb[j], mw1[(size_t)j * HM + h], acc);
    biasA[h] = acc + mb1[h];
    biasA[HM + h] = acc;
  }
}

// ---------------- CSR build ----------------
__global__ void csr_count(const int* __restrict__ eis, const int* __restrict__ eit,
                          int* __restrict__ cnt) {
  int e = blockIdx.x * 256 + threadIdx.x;
  if (e >= EB) return;
  int ss = eis[e], sd = eis[EB + e];
  atomicAdd(&cnt[0 * NN + sd], 1);
  atomicAdd(&cnt[1 * NN + ss], 1);
  int ts = eit[e], td = eit[EB + e];
  atomicAdd(&cnt[2 * NN + td], 1);
  atomicAdd(&cnt[3 * NN + ts], 1);
}

__global__ void csr_scan(const int* __restrict__ cnt, int* __restrict__ off,
                         int* __restrict__ cur) {
  int a = blockIdx.x, t = threadIdx.x;
  __shared__ int sm[NN];
  int v = cnt[a * NN + t];
  sm[t] = v; __syncthreads();
  for (int o = 1; o < NN; o <<= 1) {
    int u = (t >= o) ? sm[t - o] : 0;
    __syncthreads();
    sm[t] += u;
    __syncthreads();
  }
  int excl = sm[t] - v;
  off[a * (NN + 1) + t] = excl;
  cur[a * NN + t] = excl;
  if (t == NN - 1) off[a * (NN + 1) + NN] = sm[t];
}

__global__ void csr_fill(const int* __restrict__ eis, const int* __restrict__ eit,
                         int* __restrict__ cur, int* __restrict__ lst) {
  int e = blockIdx.x * 256 + threadIdx.x;
  if (e >= EB) return;
  int ss = eis[e], sd = eis[EB + e];
  int p = atomicAdd(&cur[0 * NN + sd], 1); lst[0 * EB + p] = ss;
  p = atomicAdd(&cur[1 * NN + ss], 1);     lst[1 * EB + p] = sd;
  int ts = eit[e], td = eit[EB + e];
  p = atomicAdd(&cur[2 * NN + td], 1);     lst[2 * EB + p] = ts;
  p = atomicAdd(&cur[3 * NN + ts], 1);     lst[3 * EB + p] = td;
}

// ---------------- bf16x3 tensor-core GEMM (ldmatrix + 3-stage cp.async) ----------------
struct P6 {
  const __nv_bfloat16* Ahi[6];   // k<512 half, row stride 512
  const __nv_bfloat16* Alo[6];
  const __nv_bfloat16* Ahi2[6];  // k>=512 (virtual concat)
  const __nv_bfloat16* Alo2[6];
  const unsigned* Bh[6];         // packed [K/2][N] words
  const unsigned* Bl[6];
  float*          Craw[6];       // nullable
  __nv_bfloat16*  Chi[6];        // nullable split epilogue
  __nv_bfloat16*  Clo[6];
  const float*    bias[6];
  int trT[6];                    // store Craw transposed [b][h][j] (Nn must be 128)
};

__device__ __forceinline__ void mma16(float* d, const unsigned* a, const unsigned* b) {
  asm volatile(
    "mma.sync.aligned.m16n8k16.row.col.f32.bf16.bf16.f32 "
    "{%0,%1,%2,%3}, {%4,%5,%6,%7}, {%8,%9}, {%0,%1,%2,%3};\n"
    : "+f"(d[0]), "+f"(d[1]), "+f"(d[2]), "+f"(d[3])
    : "r"(a[0]), "r"(a[1]), "r"(a[2]), "r"(a[3]), "r"(b[0]), "r"(b[1]));
}

__device__ __forceinline__ void ldsm4(unsigned* r, unsigned addr) {
  asm volatile("ldmatrix.sync.aligned.m8n8.x4.shared.b16 {%0,%1,%2,%3}, [%4];"
    : "=r"(r[0]), "=r"(r[1]), "=r"(r[2]), "=r"(r[3]) : "r"(addr));
}

__device__ __forceinline__ void cpa16(unsigned dst, const void* src) {
  asm volatile("cp.async.cg.shared.global [%0], [%1], 16;" :: "r"(dst), "l"(src));
}
__device__ __forceinline__ void cp_commit() { asm volatile("cp.async.commit_group;"); }

// 3-stage smem: A[3buf][2hl][BM][12w] + B[3buf][2hl][8][BN+8]
template<int BM, int BN>
constexpr int smem_b() { return (3 * 2 * BM * 12 + 3 * 2 * 8 * (BN + 8)) * 4; }

// BK=16. A fragments via ldmatrix.x4 from [m][kpair] rows (pitch 12 words);
// B fragments scalar LDS from [kpair][n] rows (pitch BN+8).
template<int BM, int BN>
__global__ __launch_bounds__(256) void gemm_bf16(P6 p, int Nn, int K) {
  constexpr int AP = 12, BP = BN + 8;
  constexpr int NAOP = 2 * BM * 2;          // 16B ops per A tile
  constexpr int NBOP = 2 * 8 * (BN / 4);    // 16B ops per B tile
  constexpr int WM = BM / 2, WN = BN / 4;
  constexpr int MI = WM / 16, NI = WN / 8;

  const int tid = threadIdx.x;
  const int z = blockIdx.z;
  const __nv_bfloat16* __restrict__ Ahi = p.Ahi[z];
  const __nv_bfloat16* __restrict__ Alo = p.Alo[z];
  const __nv_bfloat16* __restrict__ Ahi2 = p.Ahi2[z];
  const __nv_bfloat16* __restrict__ Alo2 = p.Alo2[z];
  const unsigned* __restrict__ Bh = p.Bh[z];
  const unsigned* __restrict__ Bl = p.Bl[z];
  float* __restrict__ Craw = p.Craw[z];
  __nv_bfloat16* __restrict__ Chi = p.Chi[z];
  __nv_bfloat16* __restrict__ Clo = p.Clo[z];
  const float* __restrict__ bias = p.bias[z];
  const int trT = p.trT[z];
  const int row0 = blockIdx.y * BM, col0 = blockIdx.x * BN;

  extern __shared__ unsigned smem_u[];
  unsigned* As = smem_u;
  unsigned* Bs = smem_u + 3 * 2 * BM * AP;
  const unsigned as_u = (unsigned)__cvta_generic_to_shared(As);
  const unsigned bs_u = (unsigned)__cvta_generic_to_shared(Bs);

  const int lane = tid & 31;
  const int wid = tid >> 5;
  const int gid = lane >> 2, tg = lane & 3;
  const int wr = wid >> 2, wc = wid & 3;   // 2 x 4 warps

  float acc[MI][NI][4];
#pragma unroll
  for (int i = 0; i < MI; i++)
#pragma unroll
    for (int j = 0; j < NI; j++)
#pragma unroll
      for (int q = 0; q < 4; q++) acc[i][j][q] = 0.f;

  const int nk = K >> 4;

  auto ldg = [&](int kt, int buf) {
    const __nv_bfloat16* Ah = (kt >= 512) ? Ahi2 : Ahi;
    const __nv_bfloat16* Al = (kt >= 512) ? Alo2 : Alo;
    int ko = kt & 511;
    int ktp = kt >> 1;
#pragma unroll
    for (int i = 0; i < (NAOP + 255) / 256; i++) {
      int idx = tid + i * 256;
      if (NAOP < 256 || NAOP % 256) { if (idx >= NAOP) break; }
      int hl = idx / (BM * 2);
      int rem = idx - hl * (BM * 2);
      int m = rem >> 1, ch = rem & 1;
      const __nv_bfloat16* src = (hl ? Al : Ah) + (size_t)(row0 + m) * 512 + ko + ch * 8;
      unsigned dst = as_u + (unsigned)((((buf * 2 + hl) * BM + m) * AP + ch * 4) * 4);
      cpa16(dst, src);
    }
#pragma unroll
    for (int i = 0; i < (NBOP + 255) / 256; i++) {
      int idx = tid + i * 256;
      if (NBOP < 256 || NBOP % 256) { if (idx >= NBOP) break; }
      int hl = idx / (8 * (BN / 4));
      int rem = idx - hl * (8 * (BN / 4));
      int kp = rem / (BN / 4), n4 = rem % (BN / 4);
      const unsigned* src = (hl ? Bl : Bh) + (size_t)(ktp + kp) * Nn + col0 + n4 * 4;
      unsigned dst = bs_u + (unsigned)((((buf * 2 + hl) * 8 + kp) * BP + n4 * 4) * 4);
      cpa16(dst, src);
    }
  };

  const int lrow = lane & 15;
  const int lko = (lane & 16) ? 4 : 0;

  auto compute = [&](int buf) {
    const unsigned* B0 = Bs + (size_t)((buf * 2 + 0) * 8) * BP;
    const unsigned* B1 = Bs + (size_t)((buf * 2 + 1) * 8) * BP;
    unsigned ah[MI][4], al[MI][4], bh[NI][2], bl[NI][2];
#pragma unroll
    for (int mi = 0; mi < MI; mi++) {
      int m = wr * WM + mi * 16 + lrow;
      ldsm4(ah[mi], as_u + (unsigned)((((buf * 2 + 0) * BM + m) * AP + lko) * 4));
      ldsm4(al[mi], as_u + (unsigned)((((buf * 2 + 1) * BM + m) * AP + lko) * 4));
    }
#pragma unroll
    for (int ni = 0; ni < NI; ni++) {
      int n = wc * WN + ni * 8 + gid;
      bh[ni][0] = B0[tg * BP + n];
      bh[ni][1] = B0[(tg + 4) * BP + n];
      bl[ni][0] = B1[tg * BP + n];
      bl[ni][1] = B1[(tg + 4) * BP + n];
    }
#pragma unroll
    for (int mi = 0; mi < MI; mi++)
#pragma unroll
      for (int ni = 0; ni < NI; ni++) {
        mma16(acc[mi][ni], ah[mi], bl[ni]);
        mma16(acc[mi][ni], al[mi], bh[ni]);
        mma16(acc[mi][ni], ah[mi], bh[ni]);
      }
  };

  ldg(0, 0);
  cp_commit();
  if (nk > 1) { ldg(16, 1); cp_commit(); }
  for (int t = 0; t < nk; t++) {
    int buf = t % 3;
    if (t + 1 < nk) {
      asm volatile("cp.async.wait_group 1;");
    } else {
      asm volatile("cp.async.wait_group 0;");
    }
    __syncthreads();
    if (t + 2 < nk) {
      ldg((t + 2) << 4, (t + 2) % 3);
      cp_commit();
    }
    compute(buf);
  }

#pragma unroll
  for (int mi = 0; mi < MI; mi++) {
#pragma unroll
    for (int ni = 0; ni < NI; ni++) {
      int r = row0 + wr * WM + mi * 16 + gid;
      int c = col0 + wc * WN + ni * 8 + tg * 2;
      float b0 = bias ? bias[c] : 0.f;
      float b1 = bias ? bias[c + 1] : 0.f;
      float v[4] = {acc[mi][ni][0] + b0, acc[mi][ni][1] + b1,
                    acc[mi][ni][2] + b0, acc[mi][ni][3] + b1};
      if (Craw) {
        if (trT) {
          int b_ = r >> 7, j_ = r & 127;
          int b2_ = (r + 8) >> 7, j2_ = (r + 8) & 127;
          Craw[(size_t)b_ * 16384 + (c) * 128 + j_]       = v[0];
          Craw[(size_t)b_ * 16384 + (c + 1) * 128 + j_]   = v[1];
          Craw[(size_t)b2_ * 16384 + (c) * 128 + j2_]     = v[2];
          Craw[(size_t)b2_ * 16384 + (c + 1) * 128 + j2_] = v[3];
        } else {
          size_t i0 = (size_t)r * Nn + c, i1 = (size_t)(r + 8) * Nn + c;
          Craw[i0] = v[0]; Craw[i0 + 1] = v[1];
          Craw[i1] = v[2]; Craw[i1 + 1] = v[3];
        }
      }
      if (Chi) {
        size_t i0 = (size_t)r * Nn + c, i1 = (size_t)(r + 8) * Nn + c;
        __nv_bfloat16 h, l;
        bfsplit(v[0], h, l); Chi[i0] = h;     Clo[i0] = l;
        bfsplit(v[1], h, l); Chi[i0 + 1] = h; Clo[i0 + 1] = l;
        bfsplit(v[2], h, l); Chi[i1] = h;     Clo[i1] = l;
        bfsplit(v[3], h, l); Chi[i1 + 1] = h; Clo[i1 + 1] = l;
      }
    }
  }
}

// ---------------- fused edge-mean + ReLU + LayerNorm (both sides), bf16-split out ----------------
__global__ __launch_bounds__(256)
void agg_ln(const float* __restrict__ T, const int* __restrict__ off,
            const int* __restrict__ lst,
            const float* __restrict__ gamma, const float* __restrict__ beta,
            __nv_bfloat16* __restrict__ Hhi, __nv_bfloat16* __restrict__ Hlo) {
  int n = blockIdx.x, side = blockIdx.y, t = threadIdx.x;
  const float* T1 = T + (size_t)(side * 3 + 0) * NN * C;
  const float* T2 = T + (size_t)(side * 3 + 1) * NN * C;
  const float* TR = T + (size_t)(side * 3 + 2) * NN * C;
  const int* inoff = off + (side * 2 + 0) * (NN + 1);
  const int* outoff = off + (side * 2 + 1) * (NN + 1);
  const int* inlst = lst + (size_t)(side * 2 + 0) * EB;
  const int* outlst = lst + (size_t)(side * 2 + 1) * EB;
  int c0 = t, c1 = t + 256;
  float a0 = TR[n * C + c0], a1 = TR[n * C + c1];
  {
    int s = inoff[n], e = inoff[n + 1];
    float s0 = 0.f, s1 = 0.f;
    for (int j = s; j < e; j++) {
      int m = inlst[j];
      s0 += T1[m * C + c0];
      s1 += T1[m * C + c1];
    }
    float inv = 1.0f / (float)max(e - s, 1);
    a0 += s0 * inv; a1 += s1 * inv;
  }
  {
    int s = outoff[n], e = outoff[n + 1];
    float s0 = 0.f, s1 = 0.f;
    for (int j = s; j < e; j++) {
      int m = outlst[j];
      s0 += T2[m * C + c0];
      s1 += T2[m * C + c1];
    }
    float inv = 1.0f / (float)max(e - s, 1);
    a0 += s0 * inv; a1 += s1 * inv;
  }
  a0 = fmaxf(a0, 0.f); a1 = fmaxf(a1, 0.f);
  __shared__ float red[256];
  __shared__ float mu_s, rstd_s;
  red[t] = a0 + a1; __syncthreads();
  for (int o = 128; o > 0; o >>= 1) { if (t < o) red[t] += red[t + o]; __syncthreads(); }
  if (t == 0) mu_s = red[0] * (1.0f / C);
  __syncthreads();
  float mu = mu_s;
  float d0 = a0 - mu, d1 = a1 - mu;
  __syncthreads();
  red[t] = d0 * d0 + d1 * d1; __syncthreads();
  for (int o = 128; o > 0; o >>= 1) { if (t < o) red[t] += red[t + o]; __syncthreads(); }
  if (t == 0) rstd_s = rsqrtf(red[0] * (1.0f / C) + 1e-5f);
  __syncthreads();
  float rstd = rstd_s;
  float v0 = d0 * rstd * gamma[c0] + beta[c0];
  float v1 = d1 * rstd * gamma[c1] + beta[c1];
  size_t base = (size_t)(side * NN + n) * C;
  __nv_bfloat16 h, l;
  bfsplit(v0, h, l); Hhi[base + c0] = h; Hlo[base + c0] = l;
  bfsplit(v1, h, l); Hhi[base + c1] = h; Hlo[base + c1] = l;
}

// ---------------- S_hat = Hs_b @ Ht_b^T ----------------
__global__ __launch_bounds__(256)
void shat_kernel(const float* __restrict__ Hs, const float* __restrict__ Ht,
                 float* __restrict__ Shat) {
  int b = blockIdx.z, s0 = blockIdx.y * 32, t0 = blockIdx.x * 32;
  int tid = threadIdx.x, tx = tid & 15, ty = tid >> 4;
  __shared__ float sA[32][33], sBt[32][33];
  float acc[2][2] = {};
  for (int k0 = 0; k0 < C; k0 += 32) {
#pragma unroll
    for (int l = 0; l < 4; l++) {
      int idx = tid + l * 256;
      int r = idx >> 5, k = idx & 31;
      sA[r][k] = Hs[(b * NLOC + s0 + r) * C + k0 + k];
      sBt[r][k] = Ht[(b * NLOC + t0 + r) * C + k0 + k];
    }
    __syncthreads();
#pragma unroll
    for (int k = 0; k < 32; k++) {
      float a0 = sA[ty * 2][k], a1 = sA[ty * 2 + 1][k];
      float b0 = sBt[tx * 2][k], b1 = sBt[tx * 2 + 1][k];
      acc[0][0] = fmaf(a0, b0, acc[0][0]);
      acc[0][1] = fmaf(a0, b1, acc[0][1]);
      acc[1][0] = fmaf(a1, b0, acc[1][0]);
      acc[1][1] = fmaf(a1, b1, acc[1][1]);
    }
    __syncthreads();
  }
#pragma unroll
  for (int i = 0; i < 2; i++)
#pragma unroll
    for (int j = 0; j < 2; j++)
      Shat[b * (NLOC * NLOC) + (s0 + ty * 2 + i) * NLOC + (t0 + tx * 2 + j)] = acc[i][j];
}

// ---------------- row softmax, dual output ----------------
__global__ void softmax2(const float* __restrict__ in, float* __restrict__ o1,
                         float* __restrict__ o2) {
  int row = blockIdx.x, t = threadIdx.x;
  __shared__ float red[128];
  float v = in[row * 128 + t];
  red[t] = v; __syncthreads();
  for (int o = 64; o > 0; o >>= 1) { if (t < o) red[t] = fmaxf(red[t], red[t + o]); __syncthreads(); }
  float mx = red[0]; __syncthreads();
  float e = expf(v - mx);
  red[t] = e; __syncthreads();
  for (int o = 64; o > 0; o >>= 1) { if (t < o) red[t] += red[t + o]; __syncthreads(); }
  float r = e / red[0];
  o1[row * 128 + t] = r;
  o2[row * 128 + t] = r;
}

// ---------------- R_t = S^T @ R_s, bf16-split output ----------------
__global__ __launch_bounds__(256)
void rt_kernel(const float* __restrict__ S, const float* __restrict__ Rs,
               __nv_bfloat16* __restrict__ Rthi, __nv_bfloat16* __restrict__ Rtlo) {
  int b = blockIdx.y, t0 = blockIdx.x * 16;
  int tid = threadIdx.x;
  __shared__ float sS[128][16];
#pragma unroll
  for (int l = 0; l < 8; l++) {
    int idx = tid + l * 256;
    int s = idx >> 4, tt = idx & 15;
    sS[s][tt] = S[b * (NLOC * NLOC) + s * NLOC + t0 + tt];
  }
  __syncthreads();
  int c = tid;
  float acc0[16] = {}, acc1[16] = {};
  for (int s = 0; s < NLOC; s++) {
    float r0 = Rs[(b * NLOC + s) * C + c];
    float r1 = Rs[(b * NLOC + s) * C + c + 256];
#pragma unroll
    for (int tt = 0; tt < 16; tt++) {
      float sv = sS[s][tt];
      acc0[tt] = fmaf(sv, r0, acc0[tt]);
      acc1[tt] = fmaf(sv, r1, acc1[tt]);
    }
  }
#pragma unroll
  for (int tt = 0; tt < 16; tt++) {
    size_t i0 = (size_t)(b * NLOC + t0 + tt) * C + c;
    __nv_bfloat16 h, l;
    bfsplit(acc0[tt], h, l); Rthi[i0] = h;       Rtlo[i0] = l;
    bfsplit(acc1[tt], h, l); Rthi[i0 + 256] = h; Rtlo[i0 + 256] = l;
  }
}

// ---------------- fused: S_hat += MLP pairwise; S_next = softmax(row) ----------------
__global__ void pairwise_sm(const float* __restrict__ A, const float* __restrict__ BmT,
                            const float* __restrict__ w2, const float* __restrict__ b2,
                            float* __restrict__ Shat, float* __restrict__ Sout) {
  int bi = blockIdx.x;
  int b = bi >> 7, j = threadIdx.x;
  __shared__ float sA[128], sw[128], red[128];
  sA[j] = A[bi * HM + j];
  sw[j] = w2[j];
  __syncthreads();
  float acc = 0.f;
  const float* Bp = BmT + b * (HM * NLOC) + j;
#pragma unroll 8
  for (int h = 0; h < HM; h++) {
    float d = sA[h] - Bp[h * NLOC];
    acc = fmaf(fmaxf(d, 0.f), sw[h], acc);
  }
  float val = Shat[bi * NLOC + j] + acc + b2[0];
  Shat[bi * NLOC + j] = val;
  red[j] = val; __syncthreads();
  for (int o = 64; o > 0; o >>= 1) { if (j < o) red[j] = fmaxf(red[j], red[j + o]); __syncthreads(); }
  float mx = red[0]; __syncthreads();
  float e = expf(val - mx);
  red[j] = e; __syncthreads();
  for (int o = 64; o > 0; o >>= 1) { if (j < o) red[j] += red[j + o]; __syncthreads(); }
  Sout[bi * NLOC + j] = e / red[0];
}

// ---------------- host side ----------------
struct Ptrs {
  float *T, *Hs, *Ht, *Rs, *Shat, *S, *BmT, *Am, *Wa, *biasA;
  unsigned *Wh, *Wl;
  __nv_bfloat16 *xh, *xl, *Rsh, *Rsl, *Rth, *Rtl, *Hlnh, *Hlnl;
  int *cnt, *off, *cur, *lst;
};

extern "C" void kernel_launch(void* const* d_in, const int* in_sizes, int n_in,
                              void* d_out, int out_size) {
  const float* x_s  = (const float*)d_in[0];
  const int*   ei_s = (const int*)d_in[1];
  const float* x_t  = (const float*)d_in[4];
  const int*   ei_t = (const int*)d_in[5];
  const float* e_lin1 = (const float*)d_in[8];
  const float* e_lin2 = (const float*)d_in[9];
  const float* e_rw   = (const float*)d_in[10];
  const float* e_rb   = (const float*)d_in[11];
  const float* e_g    = (const float*)d_in[12];
  const float* e_b    = (const float*)d_in[13];
  const float* e_fw   = (const float*)d_in[14];
  const float* e_fb   = (const float*)d_in[15];
  const float* c_lin1 = (const float*)d_in[16];
  const float* c_lin2 = (const float*)d_in[17];
  const float* c_rw   = (const float*)d_in[18];
  const float* c_rb   = (const float*)d_in[19];
  const float* c_g    = (const float*)d_in[20];
  const float* c_b    = (const float*)d_in[21];
  const float* c_fw   = (const float*)d_in[22];
  const float* c_fb   = (const float*)d_in[23];
  const float* m_w1   = (const float*)d_in[24];
  const float* m_b1   = (const float*)d_in[25];
  const float* m_w2   = (const float*)d_in[26];
  const float* m_b2   = (const float*)d_in[27];
  float* out = (float*)d_out;

  Ptrs q;
  cudaGetSymbolAddress((void**)&q.T,    g_T);
  cudaGetSymbolAddress((void**)&q.Hs,   g_Hs);
  cudaGetSymbolAddress((void**)&q.Ht,   g_Ht);
  cudaGetSymbolAddress((void**)&q.Rs,   g_Rs);
  cudaGetSymbolAddress((void**)&q.Shat, g_Shat);
  cudaGetSymbolAddress((void**)&q.S,    g_S);
  cudaGetSymbolAddress((void**)&q.BmT,  g_BmT);
  cudaGetSymbolAddress((void**)&q.Am,   g_Am);
  cudaGetSymbolAddress((void**)&q.Wa,   g_Wa);
  cudaGetSymbolAddress((void**)&q.biasA, g_biasA);
  cudaGetSymbolAddress((void**)&q.Wh,   g_Wh);
  cudaGetSymbolAddress((void**)&q.Wl,   g_Wl);
  cudaGetSymbolAddress((void**)&q.xh,   g_xh);
  cudaGetSymbolAddress((void**)&q.xl,   g_xl);
  cudaGetSymbolAddress((void**)&q.Rsh,  g_Rsh);
  cudaGetSymbolAddress((void**)&q.Rsl,  g_Rsl);
  cudaGetSymbolAddress((void**)&q.Rth,  g_Rth);
  cudaGetSymbolAddress((void**)&q.Rtl,  g_Rtl);
  cudaGetSymbolAddress((void**)&q.Hlnh, g_Hlnh);
  cudaGetSymbolAddress((void**)&q.Hlnl, g_Hlnl);
  cudaGetSymbolAddress((void**)&q.cnt,  g_cnt);
  cudaGetSymbolAddress((void**)&q.off,  g_off);
  cudaGetSymbolAddress((void**)&q.cur,  g_cur);
  cudaGetSymbolAddress((void**)&q.lst,  g_lst);

  cudaFuncSetAttribute(gemm_bf16<128, 128>, cudaFuncAttributeMaxDynamicSharedMemorySize, smem_b<128, 128>());
  cudaFuncSetAttribute(gemm_bf16<64, 128>,  cudaFuncAttributeMaxDynamicSharedMemorySize, smem_b<64, 128>());
  cudaFuncSetAttribute(gemm_bf16<32, 64>,   cudaFuncAttributeMaxDynamicSharedMemorySize, smem_b<32, 64>());

  // combined loop weight: Wa = c_fw@m_w1, biasA
  combine_w<<<NN + 1, HM>>>(c_fw, m_w1, c_fb, m_b1, q.Wa, q.biasA);

  // weight split+pack (once per call)
  struct { const float* src; size_t woff; int kh, n; } wj[9] = {
    {e_lin1, WO_EL1, C / 2, C}, {e_lin2, WO_EL2, C / 2, C}, {e_rw, WO_ERW, C / 2, C},
    {e_fw, WO_EFW, C, C},
    {c_lin1, WO_CL1, C / 2, C}, {c_lin2, WO_CL2, C / 2, C}, {c_rw, WO_CRW, C / 2, C},
    {q.Wa, WO_WA, NN / 2, HM},
    {nullptr, 0, 0, 0},
  };
  for (int i = 0; i < 8; i++) {
    int n = wj[i].kh * wj[i].n;
    split_pack_w<<<(n + 255) / 256, 256>>>(wj[i].src, q.Wh + wj[i].woff,
                                           q.Wl + wj[i].woff, wj[i].kh, wj[i].n);
  }
  split_a<<<NN * C / 256, 256>>>(x_s, q.xh, q.xl, NN * C);
  split_a<<<NN * C / 256, 256>>>(x_t, q.xh + NN * C, q.xl + NN * C, NN * C);

  // CSR build
  cudaMemsetAsync(q.cnt, 0, 4 * NN * sizeof(int));
  csr_count<<<(EB + 255) / 256, 256>>>(ei_s, ei_t, q.cnt);
  csr_scan<<<4, 1024>>>(q.cnt, q.off, q.cur);
  csr_fill<<<(EB + 255) / 256, 256>>>(ei_s, ei_t, q.cur, q.lst);

  // ---- embedding GNN pair (needs full concat GEMM -> Hs/Ht) ----
  {
    P6 p3 = {};
    for (int z = 0; z < 6; z++) {
      int side = z / 3, w = z % 3;
      p3.Ahi[z] = q.xh + (size_t)side * NN * C;
      p3.Alo[z] = q.xl + (size_t)side * NN * C;
      p3.Ahi2[z] = p3.Ahi[z]; p3.Alo2[z] = p3.Alo[z];
      size_t wo = (w == 0) ? WO_EL1 : (w == 1) ? WO_EL2 : WO_ERW;
      p3.Bh[z] = q.Wh + wo; p3.Bl[z] = q.Wl + wo;
      p3.Craw[z] = q.T + (size_t)z * NN * C;
      p3.bias[z] = (w == 2) ? e_rb : nullptr;
    }
    gemm_bf16<128, 128><<<dim3(C / 128, NN / 128, 6), 256, smem_b<128, 128>()>>>(p3, C, C);
    agg_ln<<<dim3(NN, 2), 256>>>(q.T, q.off, q.lst, e_g, e_b, q.Hlnh, q.Hlnl);
    P6 pc = {};
    for (int z = 0; z < 2; z++) {
      pc.Ahi[z] = q.xh + (size_t)z * NN * C;
      pc.Alo[z] = q.xl + (size_t)z * NN * C;
      pc.Ahi2[z] = q.Hlnh + (size_t)z * NN * C;
      pc.Alo2[z] = q.Hlnl + (size_t)z * NN * C;
      pc.Bh[z] = q.Wh + WO_EFW; pc.Bl[z] = q.Wl + WO_EFW;
      pc.Craw[z] = z ? q.Ht : q.Hs;
      pc.bias[z] = e_fb;
    }
    gemm_bf16<64, 128><<<dim3(C / 128, NN / 64, 2), 256, smem_b<64, 128>()>>>(pc, C, 2 * C);
  }

  shat_kernel<<<dim3(4, 4, BATCH), 256>>>(q.Hs, q.Ht, q.Shat);
  softmax2<<<NN, 128>>>(q.Shat, out, q.S);   // S_0 and first-loop S

  for (int t = 0; t < NSTEPS; t++) {
    unsigned fk0, fk1;
    tf2x32(0u, 42u, 0u, (unsigned)t, fk0, fk1);
    rng_kernel<<<RNG_N / 256, 256>>>(fk0, fk1, q.Rs, q.Rsh, q.Rsl);
    rt_kernel<<<dim3(8, BATCH), 256>>>(q.S, q.Rs, q.Rth, q.Rtl);
    // RelConv GEMMs (6z) on (Rs, Rt)
    P6 p3 = {};
    for (int z = 0; z < 6; z++) {
      int side = z / 3, w = z % 3;
      p3.Ahi[z] = side ? q.Rth : q.Rsh;
      p3.Alo[z] = side ? q.Rtl : q.Rsl;
      p3.Ahi2[z] = p3.Ahi[z]; p3.Alo2[z] = p3.Alo[z];
      size_t wo = (w == 0) ? WO_CL1 : (w == 1) ? WO_CL2 : WO_CRW;
      p3.Bh[z] = q.Wh + wo; p3.Bl[z] = q.Wl + wo;
      p3.Craw[z] = q.T + (size_t)z * NN * C;
      p3.bias[z] = (w == 2) ? c_rb : nullptr;
    }
    gemm_bf16<128, 128><<<dim3(C / 128, NN / 128, 6), 256, smem_b<128, 128>()>>>(p3, C, C);
    agg_ln<<<dim3(NN, 2), 256>>>(q.T, q.off, q.lst, c_g, c_b, q.Hlnh, q.Hlnl);
    // Fused A-GEMM: Am = [Rs|Hln_s]@Wa + biasA_s ; BmT = ([Rt|Hln_t]@Wa + biasA_t)^T
    P6 pa = {};
    for (int z = 0; z < 2; z++) {
      pa.Ahi[z] = z ? q.Rth : q.Rsh;
      pa.Alo[z] = z ? q.Rtl : q.Rsl;
      pa.Ahi2[z] = q.Hlnh + (size_t)z * NN * C;
      pa.Alo2[z] = q.Hlnl + (size_t)z * NN * C;
      pa.Bh[z] = q.Wh + WO_WA; pa.Bl[z] = q.Wl + WO_WA;
      pa.Craw[z] = z ? q.BmT : q.Am;
      pa.bias[z] = q.biasA + (z ? HM : 0);
      pa.trT[z] = z;
    }
    gemm_bf16<32, 64><<<dim3(HM / 64, NN / 32, 2), 256, smem_b<32, 64>()>>>(pa, HM, 2 * C);
    pairwise_sm<<<NN, 128>>>(q.Am, q.BmT, m_w2, m_b2, q.Shat,
                             (t == NSTEPS - 1) ? (out + SB) : q.S);
  }
}